// round 12
// baseline (speedup 1.0000x reference)
#include <cuda_runtime.h>
#include <cuda_bf16.h>
#include <cuda_fp16.h>
#include <cstdint>

// Problem constants: B=8, S=2048, H=512, G=2, V=320, D=256
#define MM 16384      // B*S
#define KK 512        // H
#define NN 640        // G*V
#define VV 320
#define DG 128        // D/G

// ---------------------------------------------------------------------------
// Scratch (static device globals: allocation-free)
// ---------------------------------------------------------------------------
__device__ __half g_logh[(size_t)MM * NN];                  // 20 MB fp16 logits
__device__ __nv_bfloat16 g_Wb[(size_t)KK * NN];             // W bf16 [K,N]
__device__ float g_marginal[NN];
__device__ float g_maskf[MM];
__device__ float g_msum;
__device__ int g_done;                                       // zero-init; reset by last block

__device__ __forceinline__ uint32_t smem_u32(const void* p) {
    uint32_t a;
    asm("{ .reg .u64 t; cvta.to.shared.u64 t, %1; cvt.u32.u64 %0, t; }" : "=r"(a) : "l"(p));
    return a;
}
__device__ __forceinline__ void cp_async16(uint32_t saddr, const void* gaddr) {
    asm volatile("cp.async.cg.shared.global [%0], [%1], 16;" :: "r"(saddr), "l"(gaddr));
}
__device__ __forceinline__ void ldmatrix_x4(uint32_t* r, uint32_t addr) {
    asm volatile("ldmatrix.sync.aligned.m8n8.x4.shared.b16 {%0,%1,%2,%3}, [%4];"
                 : "=r"(r[0]), "=r"(r[1]), "=r"(r[2]), "=r"(r[3]) : "r"(addr));
}
__device__ __forceinline__ void ldmatrix_x4_trans(uint32_t* r, uint32_t addr) {
    asm volatile("ldmatrix.sync.aligned.m8n8.x4.trans.shared.b16 {%0,%1,%2,%3}, [%4];"
                 : "=r"(r[0]), "=r"(r[1]), "=r"(r[2]), "=r"(r[3]) : "r"(addr));
}
__device__ __forceinline__ void mma16816(float* c, const uint32_t* a, uint32_t b0, uint32_t b1) {
    asm volatile("mma.sync.aligned.m16n8k16.row.col.f32.bf16.bf16.f32 "
                 "{%0,%1,%2,%3}, {%4,%5,%6,%7}, {%8,%9}, {%0,%1,%2,%3};"
                 : "+f"(c[0]), "+f"(c[1]), "+f"(c[2]), "+f"(c[3])
                 : "r"(a[0]), "r"(a[1]), "r"(a[2]), "r"(a[3]), "r"(b0), "r"(b1));
}
__device__ __forceinline__ uint32_t bf2_pack(float x, float y) {
    __nv_bfloat162 h = __floats2bfloat162_rn(x, y);
    return *(uint32_t*)&h;
}

// ---------------------------------------------------------------------------
// Pre-pass (small now): block 0 = mask init; blocks 1..80 = W fp32->bf16.
// ---------------------------------------------------------------------------
#define W4_BLOCKS 80                  // NN*KK/4 / 1024
#define PRE_GRID (1 + W4_BLOCKS)

__global__ void __launch_bounds__(1024) pre_kernel(const float* __restrict__ W,
                                                   const void* __restrict__ maskraw) {
    int bx = blockIdx.x;
    int tid = threadIdx.x;

    if (bx == 0) {
        if (tid < NN) g_marginal[tid] = 0.f;

        __shared__ int isU8;
        if (tid == 0) isU8 = 0;
        __syncthreads();

        const unsigned char* mb = (const unsigned char*)maskraw;
        int any = 0;
        for (int i = tid; i < MM; i += 1024)
            if ((i & 3) && mb[i]) any = 1;
        if (any) isU8 = 1;
        __syncthreads();

        bool u8 = (isU8 != 0);
        const int* mi = (const int*)maskraw;
        float local = 0.f;
        for (int i = tid; i < MM; i += 1024) {
            bool on = u8 ? (mb[i] != 0) : (mi[i] != 0);
            float v = on ? 1.f : 0.f;
            g_maskf[i] = v;
            local += v;
        }
        __shared__ float red[32];
        for (int o = 16; o; o >>= 1) local += __shfl_xor_sync(0xffffffffu, local, o);
        if ((tid & 31) == 0) red[tid >> 5] = local;
        __syncthreads();
        if (tid < 32) {
            float s = red[tid];
            for (int o = 16; o; o >>= 1) s += __shfl_xor_sync(0xffffffffu, s, o);
            if (tid == 0) g_msum = s;
        }
        return;
    }

    size_t i4 = (size_t)(bx - 1) * 1024 + tid;             // over NN*KK/4
    float4 v = ((const float4*)W)[i4];
    ((uint2*)g_Wb)[i4] = make_uint2(bf2_pack(v.x, v.y), bf2_pack(v.z, v.w));
}

// ---------------------------------------------------------------------------
// mma.sync bf16 GEMM with in-kernel A conversion:
//   logits[M,N] = hidden(fp32)[M,K] @ W[K,N] + bias, fp16 store.
// CTA 128x128, 512 threads (16 warps, 4m x 4n, warp tile 32x32), BK=64.
// A: LDG fp32 (prefetched 1 chunk ahead in regs) -> bf16 STS, m-major smem.
// B: cp.async bf16 from [K,N] g_Wb, k-major smem, trans ldsm. 3-stage ring.
// ---------------------------------------------------------------------------
#define BM 128
#define BN 128
#define BKC 64
#define AROWB 144                     // 64 bf16 + pad (bytes)
#define BROWB 272                     // 128 bf16 + pad (bytes)
#define NCHUNK 8
#define AB_OFF (BM * AROWB)           // 18432
#define STAGE_BYTES (AB_OFF + BKC * BROWB)   // 35840
#define GEMM_SMEM (3 * STAGE_BYTES)          // 107520

__global__ void __launch_bounds__(512) mma_gemm_kernel(const float* __restrict__ hidden,
                                                       const float* __restrict__ bias) {
    extern __shared__ char smem[];
    uint32_t sbase = smem_u32(smem);

    int tid = threadIdx.x;
    int lane = tid & 31;
    int wid = tid >> 5;
    int wr = wid >> 2;                // 0..3 (32 m-rows each)
    int wc = wid & 3;                 // 0..3 (32 n-cols each)
    int m0 = blockIdx.y * BM;
    int n0 = blockIdx.x * BN;

    float acc[2][4][4];
#pragma unroll
    for (int i = 0; i < 2; i++)
#pragma unroll
        for (int j = 0; j < 4; j++)
#pragma unroll
            for (int r = 0; r < 4; r++) acc[i][j][r] = 0.f;

    // A slots: 1024 units of 16B-bf16 (= 32B fp32); 2 per thread
    int rA0 = tid >> 3, uA0 = tid & 7;
    int rA1 = (tid + 512) >> 3, uA1 = (tid + 512) & 7;
    // B slots: 1024 segs of 16B; 2 per thread
    int rB0 = tid >> 4, sB0 = tid & 15;
    int rB1 = (tid + 512) >> 4, sB1 = (tid + 512) & 15;

    float4 ap[4];   // A prefetch regs (one chunk: 2 units x 2 float4)

#define LDG_A(kc) do {                                                        \
        int koff = (kc) * BKC;                                                \
        const float4* p0 = (const float4*)(hidden + (size_t)(m0 + rA0) * KK + koff + uA0 * 8); \
        const float4* p1 = (const float4*)(hidden + (size_t)(m0 + rA1) * KK + koff + uA1 * 8); \
        ap[0] = p0[0]; ap[1] = p0[1];                                         \
        ap[2] = p1[0]; ap[3] = p1[1];                                         \
    } while (0)

#define STS_A(st) do {                                                        \
        uint32_t sb = sbase + (st) * STAGE_BYTES;                             \
        uint4 o0, o1;                                                         \
        o0.x = bf2_pack(ap[0].x, ap[0].y); o0.y = bf2_pack(ap[0].z, ap[0].w); \
        o0.z = bf2_pack(ap[1].x, ap[1].y); o0.w = bf2_pack(ap[1].z, ap[1].w); \
        o1.x = bf2_pack(ap[2].x, ap[2].y); o1.y = bf2_pack(ap[2].z, ap[2].w); \
        o1.z = bf2_pack(ap[3].x, ap[3].y); o1.w = bf2_pack(ap[3].z, ap[3].w); \
        *(uint4*)(smem + (st) * STAGE_BYTES + rA0 * AROWB + uA0 * 16) = o0;   \
        *(uint4*)(smem + (st) * STAGE_BYTES + rA1 * AROWB + uA1 * 16) = o1;   \
        (void)sb;                                                             \
    } while (0)

#define CPASYNC_B(kc, st) do {                                                \
        int koff = (kc) * BKC;                                                \
        uint32_t sb = sbase + (st) * STAGE_BYTES;                             \
        cp_async16(sb + AB_OFF + rB0 * BROWB + sB0 * 16,                      \
                   g_Wb + (size_t)(koff + rB0) * NN + n0 + sB0 * 8);          \
        cp_async16(sb + AB_OFF + rB1 * BROWB + sB1 * 16,                      \
                   g_Wb + (size_t)(koff + rB1) * NN + n0 + sB1 * 8);          \
    } while (0)

    // Prologue
    LDG_A(0);
    STS_A(0);
    LDG_A(1);
    CPASYNC_B(0, 0); asm volatile("cp.async.commit_group;");
    CPASYNC_B(1, 1); asm volatile("cp.async.commit_group;");

    // ldmatrix per-lane offsets within a stage
    uint32_t aoff = (uint32_t)((wr * 32 + (lane & 15)) * AROWB + (lane >> 4) * 16);
    uint32_t boff = (uint32_t)(AB_OFF + ((lane & 7) + ((lane >> 3) & 1) * 8) * BROWB
                               + (wc * 32 + (lane >> 4) * 8) * 2);

    for (int kc = 0; kc < NCHUNK; kc++) {
        asm volatile("cp.async.wait_group 1;");   // B(kc) resident
        __syncthreads();                          // A(kc) STS visible too

        // stage (kc+1)%3: tenant kc-2 retired before the iter kc-1 barrier
        if (kc + 1 < NCHUNK) STS_A((kc + 1) % 3);
        if (kc + 2 < NCHUNK) { LDG_A(kc + 2); CPASYNC_B(kc + 2, (kc + 2) % 3); }
        asm volatile("cp.async.commit_group;");   // always commit

        uint32_t stb = sbase + (kc % 3) * STAGE_BYTES;
        uint32_t aBase = stb + aoff;
        uint32_t bBase = stb + boff;
#pragma unroll
        for (int kk = 0; kk < 4; kk++) {
            uint32_t afr[2][4], bfr[2][4];
#pragma unroll
            for (int mi = 0; mi < 2; mi++)
                ldmatrix_x4(afr[mi], aBase + mi * 16 * AROWB + kk * 32);
#pragma unroll
            for (int nj = 0; nj < 2; nj++)
                ldmatrix_x4_trans(bfr[nj], bBase + kk * 16 * BROWB + nj * 32);
#pragma unroll
            for (int mi = 0; mi < 2; mi++)
#pragma unroll
                for (int ni = 0; ni < 4; ni++) {
                    uint32_t b0 = bfr[ni >> 1][(ni & 1) * 2];
                    uint32_t b1 = bfr[ni >> 1][(ni & 1) * 2 + 1];
                    mma16816(acc[mi][ni], afr[mi], b0, b1);
                }
        }
    }

    // Epilogue: bias add + fp16 store
    int l4 = lane >> 2, l2 = (lane & 3) * 2;
    float2 bb[4];
#pragma unroll
    for (int ni = 0; ni < 4; ni++) {
        int col = n0 + wc * 32 + ni * 8 + l2;
        bb[ni].x = __ldg(&bias[col]);
        bb[ni].y = __ldg(&bias[col + 1]);
    }
#pragma unroll
    for (int mi = 0; mi < 2; mi++) {
        int row = m0 + wr * 32 + mi * 16 + l4;
#pragma unroll
        for (int ni = 0; ni < 4; ni++) {
            int col = n0 + wc * 32 + ni * 8 + l2;
            __half2 h0 = __floats2half2_rn(acc[mi][ni][0] + bb[ni].x, acc[mi][ni][1] + bb[ni].y);
            __half2 h1 = __floats2half2_rn(acc[mi][ni][2] + bb[ni].x, acc[mi][ni][3] + bb[ni].y);
            *(__half2*)&g_logh[(size_t)row * NN + col] = h0;
            *(__half2*)&g_logh[(size_t)(row + 8) * NN + col] = h1;
        }
    }
}

// ---------------------------------------------------------------------------
// Exact fp32 rescore of one candidate column (warp-cooperative)
// ---------------------------------------------------------------------------
__device__ __forceinline__ float exact_score(const float* __restrict__ hidden,
                                             const float* __restrict__ W,
                                             const float* __restrict__ bias,
                                             const float* __restrict__ grow,
                                             int n, int col, int v, int lane) {
    const float* hrow = hidden + (size_t)n * KK;
    float s = 0.f;
#pragma unroll 4
    for (int j = lane; j < KK; j += 32)
        s = fmaf(hrow[j], W[(size_t)j * NN + col], s);
    for (int o = 16; o; o >>= 1) s += __shfl_xor_sync(0xffffffffu, s, o);
    return s + bias[col] + grow[v];
}

// ---------------------------------------------------------------------------
// Row kernel: warp handles 4 rows of one group; marginal accumulated in
// registers across rows, then 10 smem atomics per warp. Last block computes
// perplexity. v-mapping: i -> v = 2*(lane + 32*(i/2)) + (i&1).
// ---------------------------------------------------------------------------
#define RESCORE_GAP  3.0e-2f
#define RESCORE_WIN  3.4e-2f
#define ROW_GRID 512
#define ROW_THREADS 512

__global__ void __launch_bounds__(ROW_THREADS) row_kernel(const float* __restrict__ gumbels,
                                                          const float* __restrict__ cb,
                                                          float* __restrict__ out,
                                                          const float* __restrict__ hidden,
                                                          const float* __restrict__ W,
                                                          const float* __restrict__ bias,
                                                          int out_size) {
    __shared__ float smarg[NN];
    int tid = threadIdx.x;
    for (int i = tid; i < NN; i += ROW_THREADS) smarg[i] = 0.f;
    __syncthreads();

    int warpid = tid >> 5;              // 0..15
    int lane = tid & 31;
    int g = warpid & 1;
    int nbase = (blockIdx.x * 8 + (warpid >> 1)) * 4;   // 512*8*4 = 16384 rows

#define VMAP(i) (2 * (lane + 32 * ((i) >> 1)) + ((i) & 1))

    float mreg[10];
#pragma unroll
    for (int i = 0; i < 10; i++) mreg[i] = 0.f;

    for (int q = 0; q < 4; q++) {
        int n = nbase + q;
        int w = n * 2 + g;
        const __half2* lrow2 = (const __half2*)(g_logh + (size_t)n * NN + g * VV);
        const float* grow = gumbels + (size_t)w * VV;
        const float2* grow2 = (const float2*)grow;

        float l[10], sc[10];
#pragma unroll
        for (int j = 0; j < 5; j++) {
            float2 lf = __half22float2(lrow2[lane + 32 * j]);
            float2 gg = grow2[lane + 32 * j];
            l[2 * j] = lf.x;     l[2 * j + 1] = lf.y;
            sc[2 * j] = lf.x + gg.x;
            sc[2 * j + 1] = lf.y + gg.y;
        }

        // argmax of logits + gumbels
        float best = -3.4e38f;
        int bidx = 0;
#pragma unroll
        for (int i = 0; i < 10; i++) {
            int v = VMAP(i);
            if (sc[i] > best || (sc[i] == best && v < bidx)) { best = sc[i]; bidx = v; }
        }
        for (int o = 16; o; o >>= 1) {
            float ob = __shfl_down_sync(0xffffffffu, best, o);
            int oi   = __shfl_down_sync(0xffffffffu, bidx, o);
            if (ob > best || (ob == best && oi < bidx)) { best = ob; bidx = oi; }
        }
        best = __shfl_sync(0xffffffffu, best, 0);
        bidx = __shfl_sync(0xffffffffu, bidx, 0);

        // second best (excluding bidx)
        float sec = -3.4e38f;
#pragma unroll
        for (int i = 0; i < 10; i++) {
            int v = VMAP(i);
            if (v != bidx && sc[i] > sec) sec = sc[i];
        }
        for (int o = 16; o; o >>= 1) sec = fmaxf(sec, __shfl_xor_sync(0xffffffffu, sec, o));

        // near-tie: exact fp32 rescore of candidates within the window
        if (best - sec < RESCORE_GAP) {
            float thr = best - RESCORE_WIN;
            float exbest = -3.4e38f;
            int exidx = VV;
            int col0 = g * VV;
#pragma unroll
            for (int i = 0; i < 10; i++) {
                unsigned mset = __ballot_sync(0xffffffffu, sc[i] >= thr);
                while (mset) {
                    int src = __ffs(mset) - 1;
                    mset &= mset - 1;
                    int v = 2 * (src + 32 * (i >> 1)) + (i & 1);
                    float ex = exact_score(hidden, W, bias, grow, n, col0 + v, v, lane);
                    if (ex > exbest || (ex == exbest && v < exidx)) { exbest = ex; exidx = v; }
                }
            }
            bidx = exidx;
        }

        // softmax(logits) for marginal
        float mx = l[0];
#pragma unroll
        for (int i = 1; i < 10; i++) mx = fmaxf(mx, l[i]);
        for (int o = 16; o; o >>= 1) mx = fmaxf(mx, __shfl_xor_sync(0xffffffffu, mx, o));
        float e[10];
        float sum = 0.f;
#pragma unroll
        for (int i = 0; i < 10; i++) { e[i] = __expf(l[i] - mx); sum += e[i]; }
        for (int o = 16; o; o >>= 1) sum += __shfl_xor_sync(0xffffffffu, sum, o);

        if (g_maskf[n] != 0.f) {
            float inv = 1.f / sum;
#pragma unroll
            for (int i = 0; i < 10; i++) mreg[i] = fmaf(e[i], inv, mreg[i]);
        }

        // codevector gather
        const float4* c4 = (const float4*)(cb + (size_t)(g * VV + bidx) * DG);
        float4* o4 = (float4*)(out + (size_t)n * 256 + g * DG);
        o4[lane] = c4[lane];
    }

    // one batch of smem atomics per warp (4 rows folded in registers)
#pragma unroll
    for (int i = 0; i < 10; i++)
        atomicAdd(&smarg[g * VV + VMAP(i)], mreg[i]);

    __syncthreads();
    for (int i = tid; i < NN; i += ROW_THREADS) atomicAdd(&g_marginal[i], smarg[i]);

    // ---- merged finalization: last block computes perplexity ----
    __shared__ int amLast;
    __threadfence();
    __syncthreads();
    if (tid == 0) amLast = (atomicAdd(&g_done, 1) == ROW_GRID - 1);
    __syncthreads();
    if (amLast) {
        __threadfence();   // acquire marginal written by all blocks
        __shared__ float s2[2];
        if (tid < 2) s2[tid] = 0.f;
        __syncthreads();
        float t0 = 0.f, t1 = 0.f;
        for (int i = tid; i < NN; i += ROW_THREADS) {
            float val = g_marginal[i] / g_msum;
            float t = val * logf(val + 1e-7f);
            if (i < VV) t0 += t; else t1 += t;
        }
        for (int o = 16; o; o >>= 1) {
            t0 += __shfl_xor_sync(0xffffffffu, t0, o);
            t1 += __shfl_xor_sync(0xffffffffu, t1, o);
        }
        if (lane == 0) { atomicAdd(&s2[0], t0); atomicAdd(&s2[1], t1); }
        __syncthreads();
        if (tid == 0) {
            out[out_size - 1] = expf(-s2[0]) + expf(-s2[1]);
            g_done = 0;   // reset for next graph replay
        }
    }
}

// ---------------------------------------------------------------------------
extern "C" void kernel_launch(void* const* d_in, const int* in_sizes, int n_in,
                              void* d_out, int out_size) {
    const float* hidden = (const float*)d_in[0];   // [8,2048,512]
    const void*  mask   = d_in[1];                 // [8,2048]
    const float* W      = (const float*)d_in[2];   // [512,640]
    const float* b      = (const float*)d_in[3];   // [640]
    const float* cb     = (const float*)d_in[4];   // [1,640,128]
    const float* gum    = (const float*)d_in[5];   // [32768,320]
    float* out = (float*)d_out;

    cudaFuncSetAttribute(mma_gemm_kernel,
                         cudaFuncAttributeMaxDynamicSharedMemorySize, GEMM_SMEM);

    pre_kernel<<<PRE_GRID, 1024>>>(W, mask);

    dim3 ggrid(NN / BN, MM / BM);   // (5, 128)
    mma_gemm_kernel<<<ggrid, 512, GEMM_SMEM>>>(hidden, b);

    row_kernel<<<ROW_GRID, ROW_THREADS>>>(gum, cb, out, hidden, W, b, out_size);
}

// round 13
// speedup vs baseline: 1.1612x; 1.1612x over previous
#include <cuda_runtime.h>
#include <cuda_bf16.h>
#include <cuda_fp16.h>
#include <cstdint>

// Problem constants: B=8, S=2048, H=512, G=2, V=320, D=256
#define MM 16384      // B*S
#define KK 512        // H
#define NN 640        // G*V
#define VV 320
#define DG 128        // D/G

// ---------------------------------------------------------------------------
// Scratch (static device globals: allocation-free)
// ---------------------------------------------------------------------------
__device__ __half g_logh[(size_t)MM * NN];                  // 20 MB fp16 logits
__device__ __nv_bfloat16 g_Ah[(size_t)MM * KK];             // hidden bf16 [M,K]
__device__ __nv_bfloat16 g_Wb[(size_t)KK * NN];             // W bf16 [K,N]
__device__ float g_marginal[NN];
__device__ float g_maskf[MM];
__device__ float g_msum;
__device__ int g_done;                                       // zero-init; reset by last block

__device__ __forceinline__ uint32_t smem_u32(const void* p) {
    uint32_t a;
    asm("{ .reg .u64 t; cvta.to.shared.u64 t, %1; cvt.u32.u64 %0, t; }" : "=r"(a) : "l"(p));
    return a;
}
__device__ __forceinline__ void cp_async16(uint32_t saddr, const void* gaddr) {
    asm volatile("cp.async.cg.shared.global [%0], [%1], 16;" :: "r"(saddr), "l"(gaddr));
}
__device__ __forceinline__ void ldmatrix_x4(uint32_t* r, uint32_t addr) {
    asm volatile("ldmatrix.sync.aligned.m8n8.x4.shared.b16 {%0,%1,%2,%3}, [%4];"
                 : "=r"(r[0]), "=r"(r[1]), "=r"(r[2]), "=r"(r[3]) : "r"(addr));
}
__device__ __forceinline__ void ldmatrix_x4_trans(uint32_t* r, uint32_t addr) {
    asm volatile("ldmatrix.sync.aligned.m8n8.x4.trans.shared.b16 {%0,%1,%2,%3}, [%4];"
                 : "=r"(r[0]), "=r"(r[1]), "=r"(r[2]), "=r"(r[3]) : "r"(addr));
}
__device__ __forceinline__ void mma16816(float* c, const uint32_t* a, uint32_t b0, uint32_t b1) {
    asm volatile("mma.sync.aligned.m16n8k16.row.col.f32.bf16.bf16.f32 "
                 "{%0,%1,%2,%3}, {%4,%5,%6,%7}, {%8,%9}, {%0,%1,%2,%3};"
                 : "+f"(c[0]), "+f"(c[1]), "+f"(c[2]), "+f"(c[3])
                 : "r"(a[0]), "r"(a[1]), "r"(a[2]), "r"(a[3]), "r"(b0), "r"(b1));
}
__device__ __forceinline__ uint32_t bf2_pack(float x, float y) {
    __nv_bfloat162 h = __floats2bfloat162_rn(x, y);
    return *(uint32_t*)&h;
}

// ---------------------------------------------------------------------------
// Fused pre-pass:
//   block 0         : init (zero marginal, VECTORIZED mask detect/expand/sum)
//   blocks 1..80    : convert W fp32 [K,N] -> bf16 [K,N] (float4, coalesced)
//   blocks 81..2128 : convert hidden fp32 -> bf16 (1 float4 per thread)
// ---------------------------------------------------------------------------
#define W4_BLOCKS 80                  // NN*KK/4 / 1024
#define A4_BLOCKS 2048                // MM*KK/4 / 1024
#define PRE_GRID (1 + W4_BLOCKS + A4_BLOCKS)

__global__ void __launch_bounds__(1024) pre_kernel(const float* __restrict__ A,
                                                   const float* __restrict__ W,
                                                   const void* __restrict__ maskraw) {
    int bx = blockIdx.x;
    int tid = threadIdx.x;

    if (bx == 0) {
        if (tid < NN) g_marginal[tid] = 0.f;

        __shared__ int isU8;
        if (tid == 0) isU8 = 0;
        __syncthreads();

        // Detection: one uint4 per thread covers bytes 16*tid..16*tid+15
        // (16 KB total — full u8 buffer / first quarter of an int32 buffer).
        // Little-endian: bytes at global pos%4!=0 are bits 8..31 of each word.
        const uint4* m16 = (const uint4*)maskraw;
        uint4 d = m16[tid];
        if (((d.x | d.y | d.z | d.w) & 0xFFFFFF00u) != 0u) isU8 = 1;
        __syncthreads();

        float local = 0.f;
        if (isU8) {
            // d already holds this thread's 16 u8 entries
            unsigned wv[4] = {d.x, d.y, d.z, d.w};
            float4 st[4];
#pragma unroll
            for (int wd = 0; wd < 4; wd++) {
                float* f = (float*)&st[wd];
#pragma unroll
                for (int byt = 0; byt < 4; byt++) {
                    float v = ((wv[wd] >> (8 * byt)) & 0xFFu) ? 1.f : 0.f;
                    f[byt] = v;
                    local += v;
                }
            }
#pragma unroll
            for (int wd = 0; wd < 4; wd++)
                *(float4*)&g_maskf[tid * 16 + wd * 4] = st[wd];
        } else {
            // int32: 16384 words; 4 uint4 rounds of 4 entries each
            const uint4* mi4 = (const uint4*)maskraw;
#pragma unroll
            for (int it = 0; it < 4; it++) {
                uint4 wv = mi4[tid + it * 1024];
                int base = 4 * (tid + it * 1024);
                float4 st;
                st.x = wv.x ? 1.f : 0.f;
                st.y = wv.y ? 1.f : 0.f;
                st.z = wv.z ? 1.f : 0.f;
                st.w = wv.w ? 1.f : 0.f;
                local += st.x + st.y + st.z + st.w;
                *(float4*)&g_maskf[base] = st;
            }
        }

        __shared__ float red[32];
        for (int o = 16; o; o >>= 1) local += __shfl_xor_sync(0xffffffffu, local, o);
        if ((tid & 31) == 0) red[tid >> 5] = local;
        __syncthreads();
        if (tid < 32) {
            float s = red[tid];
            for (int o = 16; o; o >>= 1) s += __shfl_xor_sync(0xffffffffu, s, o);
            if (tid == 0) g_msum = s;
        }
        return;
    }

    if (bx <= W4_BLOCKS) {
        size_t i4 = (size_t)(bx - 1) * 1024 + tid;             // over NN*KK/4
        float4 v = ((const float4*)W)[i4];
        ((uint2*)g_Wb)[i4] = make_uint2(bf2_pack(v.x, v.y), bf2_pack(v.z, v.w));
    } else {
        size_t i4 = (size_t)(bx - 1 - W4_BLOCKS) * 1024 + tid; // over MM*KK/4
        float4 v = ((const float4*)A)[i4];
        ((uint2*)g_Ah)[i4] = make_uint2(bf2_pack(v.x, v.y), bf2_pack(v.z, v.w));
    }
}

// ---------------------------------------------------------------------------
// mma.sync bf16 GEMM: logits[M,N] = A @ W + bias, fp16 store.
// CTA 128x128, 8 warps (64x32 each), BK=64, 3-stage cp.async ring.
// A: m-major smem (pitch 144B), non-trans ldsm. B: k-major smem (pitch 272B),
// trans ldsm straight from the [K,N] bf16 copy of W.
// ---------------------------------------------------------------------------
#define BM 128
#define BN 128
#define BKC 64
#define AROWB 144                     // 64 bf16 + pad
#define BROWB 272                     // 128 bf16 + pad
#define NCHUNK 8
#define STAGES 3
#define AB_OFF (BM * AROWB)           // 18432
#define STAGE_BYTES (AB_OFF + BKC * BROWB)   // 35840
#define GEMM_SMEM (STAGES * STAGE_BYTES)     // 107520

__global__ void __launch_bounds__(256, 2) mma_gemm_kernel(const float* __restrict__ bias) {
    extern __shared__ char smem[];
    uint32_t sbase = smem_u32(smem);

    int tid = threadIdx.x;
    int lane = tid & 31;
    int wid = tid >> 5;
    int wr = wid >> 2;
    int wc = wid & 3;
    int m0 = blockIdx.y * BM;
    int n0 = blockIdx.x * BN;

    float acc[4][4][4];
#pragma unroll
    for (int i = 0; i < 4; i++)
#pragma unroll
        for (int j = 0; j < 4; j++)
#pragma unroll
            for (int r = 0; r < 4; r++) acc[i][j][r] = 0.f;

    int rowA = tid >> 3, segA = tid & 7;   // A: 1024 segs of 16B (4 iters)
    int rowB = tid >> 4, segB = tid & 15;  // B: 1024 segs of 16B (4 iters)

#define LOAD_CHUNK(kc, st) do {                                               \
        int koff = (kc) * BKC;                                                \
        uint32_t sb = sbase + (st) * STAGE_BYTES;                             \
        _Pragma("unroll")                                                     \
        for (int p = 0; p < 4; p++) {                                         \
            int r = rowA + 32 * p;                                            \
            cp_async16(sb + r * AROWB + segA * 16,                            \
                       g_Ah + (size_t)(m0 + r) * KK + koff + segA * 8);       \
        }                                                                     \
        _Pragma("unroll")                                                     \
        for (int p = 0; p < 4; p++) {                                         \
            int r = rowB + 16 * p;                                            \
            cp_async16(sb + AB_OFF + r * BROWB + segB * 16,                   \
                       g_Wb + (size_t)(koff + r) * NN + n0 + segB * 8);       \
        }                                                                     \
    } while (0)

    LOAD_CHUNK(0, 0); asm volatile("cp.async.commit_group;");
    LOAD_CHUNK(1, 1); asm volatile("cp.async.commit_group;");

    uint32_t aoff = (uint32_t)((wr * 64 + (lane & 15)) * AROWB + (lane >> 4) * 16);
    uint32_t boff = (uint32_t)(AB_OFF + ((lane & 7) + ((lane >> 3) & 1) * 8) * BROWB
                               + (wc * 32 + (lane >> 4) * 8) * 2);

    for (int kc = 0; kc < NCHUNK; kc++) {
        asm volatile("cp.async.wait_group 1;");
        __syncthreads();

        if (kc + 2 < NCHUNK) LOAD_CHUNK(kc + 2, (kc + 2) % 3);
        asm volatile("cp.async.commit_group;");

        uint32_t stb = sbase + (kc % 3) * STAGE_BYTES;
        uint32_t aBase = stb + aoff;
        uint32_t bBase = stb + boff;
#pragma unroll
        for (int kk = 0; kk < 4; kk++) {
            uint32_t afr[4][4], bfr[2][4];
#pragma unroll
            for (int mi = 0; mi < 4; mi++)
                ldmatrix_x4(afr[mi], aBase + mi * 16 * AROWB + kk * 32);
#pragma unroll
            for (int nj = 0; nj < 2; nj++)
                ldmatrix_x4_trans(bfr[nj], bBase + kk * 16 * BROWB + nj * 32);
#pragma unroll
            for (int mi = 0; mi < 4; mi++)
#pragma unroll
                for (int ni = 0; ni < 4; ni++) {
                    uint32_t b0 = bfr[ni >> 1][(ni & 1) * 2];
                    uint32_t b1 = bfr[ni >> 1][(ni & 1) * 2 + 1];
                    mma16816(acc[mi][ni], afr[mi], b0, b1);
                }
        }
    }

    // Epilogue: bias add + fp16 store
    int l4 = lane >> 2, l2 = (lane & 3) * 2;
    float2 bb[4];
#pragma unroll
    for (int ni = 0; ni < 4; ni++) {
        int col = n0 + wc * 32 + ni * 8 + l2;
        bb[ni].x = __ldg(&bias[col]);
        bb[ni].y = __ldg(&bias[col + 1]);
    }
#pragma unroll
    for (int mi = 0; mi < 4; mi++) {
        int row = m0 + wr * 64 + mi * 16 + l4;
#pragma unroll
        for (int ni = 0; ni < 4; ni++) {
            int col = n0 + wc * 32 + ni * 8 + l2;
            __half2 h0 = __floats2half2_rn(acc[mi][ni][0] + bb[ni].x, acc[mi][ni][1] + bb[ni].y);
            __half2 h1 = __floats2half2_rn(acc[mi][ni][2] + bb[ni].x, acc[mi][ni][3] + bb[ni].y);
            *(__half2*)&g_logh[(size_t)row * NN + col] = h0;
            *(__half2*)&g_logh[(size_t)(row + 8) * NN + col] = h1;
        }
    }
}

// ---------------------------------------------------------------------------
// Exact fp32 rescore of one candidate column (warp-cooperative)
// ---------------------------------------------------------------------------
__device__ __forceinline__ float exact_score(const float* __restrict__ hidden,
                                             const float* __restrict__ W,
                                             const float* __restrict__ bias,
                                             const float* __restrict__ grow,
                                             int n, int col, int v, int lane) {
    const float* hrow = hidden + (size_t)n * KK;
    float s = 0.f;
#pragma unroll 4
    for (int j = lane; j < KK; j += 32)
        s = fmaf(hrow[j], W[(size_t)j * NN + col], s);
    for (int o = 16; o; o >>= 1) s += __shfl_xor_sync(0xffffffffu, s, o);
    return s + bias[col] + grow[v];
}

// ---------------------------------------------------------------------------
// Row kernel: warp handles 4 rows of one group; marginal accumulated in
// registers across rows, then 10 smem atomics per warp. Last block computes
// perplexity. v-mapping: i -> v = 2*(lane + 32*(i/2)) + (i&1).
// ---------------------------------------------------------------------------
#define RESCORE_GAP  3.0e-2f
#define RESCORE_WIN  3.4e-2f
#define ROW_GRID 512
#define ROW_THREADS 512

__global__ void __launch_bounds__(ROW_THREADS) row_kernel(const float* __restrict__ gumbels,
                                                          const float* __restrict__ cb,
                                                          float* __restrict__ out,
                                                          const float* __restrict__ hidden,
                                                          const float* __restrict__ W,
                                                          const float* __restrict__ bias,
                                                          int out_size) {
    __shared__ float smarg[NN];
    int tid = threadIdx.x;
    for (int i = tid; i < NN; i += ROW_THREADS) smarg[i] = 0.f;
    __syncthreads();

    int warpid = tid >> 5;              // 0..15
    int lane = tid & 31;
    int g = warpid & 1;
    int nbase = (blockIdx.x * 8 + (warpid >> 1)) * 4;   // 512*8*4 = 16384 rows

#define VMAP(i) (2 * (lane + 32 * ((i) >> 1)) + ((i) & 1))

    float mreg[10];
#pragma unroll
    for (int i = 0; i < 10; i++) mreg[i] = 0.f;

    for (int q = 0; q < 4; q++) {
        int n = nbase + q;
        int w = n * 2 + g;
        const __half2* lrow2 = (const __half2*)(g_logh + (size_t)n * NN + g * VV);
        const float* grow = gumbels + (size_t)w * VV;
        const float2* grow2 = (const float2*)grow;

        float l[10], sc[10];
#pragma unroll
        for (int j = 0; j < 5; j++) {
            float2 lf = __half22float2(lrow2[lane + 32 * j]);
            float2 gg = grow2[lane + 32 * j];
            l[2 * j] = lf.x;     l[2 * j + 1] = lf.y;
            sc[2 * j] = lf.x + gg.x;
            sc[2 * j + 1] = lf.y + gg.y;
        }

        // argmax of logits + gumbels
        float best = -3.4e38f;
        int bidx = 0;
#pragma unroll
        for (int i = 0; i < 10; i++) {
            int v = VMAP(i);
            if (sc[i] > best || (sc[i] == best && v < bidx)) { best = sc[i]; bidx = v; }
        }
        for (int o = 16; o; o >>= 1) {
            float ob = __shfl_down_sync(0xffffffffu, best, o);
            int oi   = __shfl_down_sync(0xffffffffu, bidx, o);
            if (ob > best || (ob == best && oi < bidx)) { best = ob; bidx = oi; }
        }
        best = __shfl_sync(0xffffffffu, best, 0);
        bidx = __shfl_sync(0xffffffffu, bidx, 0);

        // second best (excluding bidx)
        float sec = -3.4e38f;
#pragma unroll
        for (int i = 0; i < 10; i++) {
            int v = VMAP(i);
            if (v != bidx && sc[i] > sec) sec = sc[i];
        }
        for (int o = 16; o; o >>= 1) sec = fmaxf(sec, __shfl_xor_sync(0xffffffffu, sec, o));

        // near-tie: exact fp32 rescore of candidates within the window
        if (best - sec < RESCORE_GAP) {
            float thr = best - RESCORE_WIN;
            float exbest = -3.4e38f;
            int exidx = VV;
            int col0 = g * VV;
#pragma unroll
            for (int i = 0; i < 10; i++) {
                unsigned mset = __ballot_sync(0xffffffffu, sc[i] >= thr);
                while (mset) {
                    int src = __ffs(mset) - 1;
                    mset &= mset - 1;
                    int v = 2 * (src + 32 * (i >> 1)) + (i & 1);
                    float ex = exact_score(hidden, W, bias, grow, n, col0 + v, v, lane);
                    if (ex > exbest || (ex == exbest && v < exidx)) { exbest = ex; exidx = v; }
                }
            }
            bidx = exidx;
        }

        // softmax(logits) for marginal
        float mx = l[0];
#pragma unroll
        for (int i = 1; i < 10; i++) mx = fmaxf(mx, l[i]);
        for (int o = 16; o; o >>= 1) mx = fmaxf(mx, __shfl_xor_sync(0xffffffffu, mx, o));
        float e[10];
        float sum = 0.f;
#pragma unroll
        for (int i = 0; i < 10; i++) { e[i] = __expf(l[i] - mx); sum += e[i]; }
        for (int o = 16; o; o >>= 1) sum += __shfl_xor_sync(0xffffffffu, sum, o);

        if (g_maskf[n] != 0.f) {
            float inv = 1.f / sum;
#pragma unroll
            for (int i = 0; i < 10; i++) mreg[i] = fmaf(e[i], inv, mreg[i]);
        }

        // codevector gather
        const float4* c4 = (const float4*)(cb + (size_t)(g * VV + bidx) * DG);
        float4* o4 = (float4*)(out + (size_t)n * 256 + g * DG);
        o4[lane] = c4[lane];
    }

    // one batch of smem atomics per warp (4 rows folded in registers)
#pragma unroll
    for (int i = 0; i < 10; i++)
        atomicAdd(&smarg[g * VV + VMAP(i)], mreg[i]);

    __syncthreads();
    for (int i = tid; i < NN; i += ROW_THREADS) atomicAdd(&g_marginal[i], smarg[i]);

    // ---- merged finalization: last block computes perplexity ----
    __shared__ int amLast;
    __threadfence();
    __syncthreads();
    if (tid == 0) amLast = (atomicAdd(&g_done, 1) == ROW_GRID - 1);
    __syncthreads();
    if (amLast) {
        __threadfence();   // acquire marginal written by all blocks
        __shared__ float s2[2];
        if (tid < 2) s2[tid] = 0.f;
        __syncthreads();
        float t0 = 0.f, t1 = 0.f;
        for (int i = tid; i < NN; i += ROW_THREADS) {
            float val = g_marginal[i] / g_msum;
            float t = val * logf(val + 1e-7f);
            if (i < VV) t0 += t; else t1 += t;
        }
        for (int o = 16; o; o >>= 1) {
            t0 += __shfl_xor_sync(0xffffffffu, t0, o);
            t1 += __shfl_xor_sync(0xffffffffu, t1, o);
        }
        if (lane == 0) { atomicAdd(&s2[0], t0); atomicAdd(&s2[1], t1); }
        __syncthreads();
        if (tid == 0) {
            out[out_size - 1] = expf(-s2[0]) + expf(-s2[1]);
            g_done = 0;   // reset for next graph replay
        }
    }
}

// ---------------------------------------------------------------------------
extern "C" void kernel_launch(void* const* d_in, const int* in_sizes, int n_in,
                              void* d_out, int out_size) {
    const float* hidden = (const float*)d_in[0];   // [8,2048,512]
    const void*  mask   = d_in[1];                 // [8,2048]
    const float* W      = (const float*)d_in[2];   // [512,640]
    const float* b      = (const float*)d_in[3];   // [640]
    const float* cb     = (const float*)d_in[4];   // [1,640,128]
    const float* gum    = (const float*)d_in[5];   // [32768,320]
    float* out = (float*)d_out;

    cudaFuncSetAttribute(mma_gemm_kernel,
                         cudaFuncAttributeMaxDynamicSharedMemorySize, GEMM_SMEM);

    pre_kernel<<<PRE_GRID, 1024>>>(hidden, W, mask);

    dim3 ggrid(NN / BN, MM / BM);   // (5, 128)
    mma_gemm_kernel<<<ggrid, 256, GEMM_SMEM>>>(b);

    row_kernel<<<ROW_GRID, ROW_THREADS>>>(gum, cb, out, hidden, W, b, out_size);
}

// round 15
// speedup vs baseline: 1.2387x; 1.0668x over previous
#include <cuda_runtime.h>
#include <cuda_bf16.h>
#include <cuda_fp16.h>
#include <cstdint>

// Problem constants: B=8, S=2048, H=512, G=2, V=320, D=256
#define MM 16384      // B*S
#define KK 512        // H
#define NN 640        // G*V
#define VV 320
#define DG 128        // D/G

// ---------------------------------------------------------------------------
// Scratch (static device globals: allocation-free)
// ---------------------------------------------------------------------------
__device__ __half g_logh[(size_t)MM * NN];                  // 20 MB fp16 logits
__device__ __nv_bfloat16 g_Ah[(size_t)MM * KK];             // hidden bf16 [M,K]
__device__ __nv_bfloat16 g_Wb[(size_t)KK * NN];             // W bf16 [K,N]
__device__ float g_marginal[NN];
__device__ float g_maskf[MM];
__device__ float g_msum;
__device__ int g_done;                                       // zero-init; reset by last block

__device__ __forceinline__ uint32_t smem_u32(const void* p) {
    uint32_t a;
    asm("{ .reg .u64 t; cvta.to.shared.u64 t, %1; cvt.u32.u64 %0, t; }" : "=r"(a) : "l"(p));
    return a;
}
__device__ __forceinline__ void cp_async16(uint32_t saddr, const void* gaddr) {
    asm volatile("cp.async.cg.shared.global [%0], [%1], 16;" :: "r"(saddr), "l"(gaddr));
}
__device__ __forceinline__ void ldmatrix_x4(uint32_t* r, uint32_t addr) {
    asm volatile("ldmatrix.sync.aligned.m8n8.x4.shared.b16 {%0,%1,%2,%3}, [%4];"
                 : "=r"(r[0]), "=r"(r[1]), "=r"(r[2]), "=r"(r[3]) : "r"(addr));
}
__device__ __forceinline__ void ldmatrix_x4_trans(uint32_t* r, uint32_t addr) {
    asm volatile("ldmatrix.sync.aligned.m8n8.x4.trans.shared.b16 {%0,%1,%2,%3}, [%4];"
                 : "=r"(r[0]), "=r"(r[1]), "=r"(r[2]), "=r"(r[3]) : "r"(addr));
}
__device__ __forceinline__ void mma16816(float* c, const uint32_t* a, uint32_t b0, uint32_t b1) {
    asm volatile("mma.sync.aligned.m16n8k16.row.col.f32.bf16.bf16.f32 "
                 "{%0,%1,%2,%3}, {%4,%5,%6,%7}, {%8,%9}, {%0,%1,%2,%3};"
                 : "+f"(c[0]), "+f"(c[1]), "+f"(c[2]), "+f"(c[3])
                 : "r"(a[0]), "r"(a[1]), "r"(a[2]), "r"(a[3]), "r"(b0), "r"(b1));
}
__device__ __forceinline__ uint32_t bf2_pack(float x, float y) {
    __nv_bfloat162 h = __floats2bfloat162_rn(x, y);
    return *(uint32_t*)&h;
}

// ---------------------------------------------------------------------------
// Fused pre-pass:
//   block 0          : init (zero marginal, VECTORIZED mask detect/expand/sum)
//   blocks 1..80     : convert W fp32 [K,N] -> bf16 [K,N] (float4, coalesced)
//   blocks 81..1104  : convert hidden fp32 -> bf16 (2 float4 per thread, ILP 2)
// ---------------------------------------------------------------------------
#define W4_BLOCKS 80                  // NN*KK/4 / 1024
#define A4_BLOCKS 1024                // MM*KK/4 / 2048
#define PRE_GRID (1 + W4_BLOCKS + A4_BLOCKS)

__global__ void __launch_bounds__(1024) pre_kernel(const float* __restrict__ A,
                                                   const float* __restrict__ W,
                                                   const void* __restrict__ maskraw) {
    int bx = blockIdx.x;
    int tid = threadIdx.x;

    if (bx == 0) {
        if (tid < NN) g_marginal[tid] = 0.f;

        __shared__ int isU8;
        if (tid == 0) isU8 = 0;
        __syncthreads();

        // Detection: one uint4 per thread covers bytes 16*tid..16*tid+15.
        // Little-endian: bytes at global pos%4!=0 are bits 8..31 of each word.
        const uint4* m16 = (const uint4*)maskraw;
        uint4 d = m16[tid];
        if (((d.x | d.y | d.z | d.w) & 0xFFFFFF00u) != 0u) isU8 = 1;
        __syncthreads();

        float local = 0.f;
        if (isU8) {
            unsigned wv[4] = {d.x, d.y, d.z, d.w};
            float4 st[4];
#pragma unroll
            for (int wd = 0; wd < 4; wd++) {
                float* f = (float*)&st[wd];
#pragma unroll
                for (int byt = 0; byt < 4; byt++) {
                    float v = ((wv[wd] >> (8 * byt)) & 0xFFu) ? 1.f : 0.f;
                    f[byt] = v;
                    local += v;
                }
            }
#pragma unroll
            for (int wd = 0; wd < 4; wd++)
                *(float4*)&g_maskf[tid * 16 + wd * 4] = st[wd];
        } else {
            const uint4* mi4 = (const uint4*)maskraw;
#pragma unroll
            for (int it = 0; it < 4; it++) {
                uint4 wv = mi4[tid + it * 1024];
                int base = 4 * (tid + it * 1024);
                float4 st;
                st.x = wv.x ? 1.f : 0.f;
                st.y = wv.y ? 1.f : 0.f;
                st.z = wv.z ? 1.f : 0.f;
                st.w = wv.w ? 1.f : 0.f;
                local += st.x + st.y + st.z + st.w;
                *(float4*)&g_maskf[base] = st;
            }
        }

        __shared__ float red[32];
        for (int o = 16; o; o >>= 1) local += __shfl_xor_sync(0xffffffffu, local, o);
        if ((tid & 31) == 0) red[tid >> 5] = local;
        __syncthreads();
        if (tid < 32) {
            float s = red[tid];
            for (int o = 16; o; o >>= 1) s += __shfl_xor_sync(0xffffffffu, s, o);
            if (tid == 0) g_msum = s;
        }
        return;
    }

    if (bx <= W4_BLOCKS) {
        size_t i4 = (size_t)(bx - 1) * 1024 + tid;             // over NN*KK/4
        float4 v = ((const float4*)W)[i4];
        ((uint2*)g_Wb)[i4] = make_uint2(bf2_pack(v.x, v.y), bf2_pack(v.z, v.w));
    } else {
        size_t base = (size_t)(bx - 1 - W4_BLOCKS) * 2048 + tid; // over MM*KK/4
        float4 v0 = ((const float4*)A)[base];
        float4 v1 = ((const float4*)A)[base + 1024];
        ((uint2*)g_Ah)[base]        = make_uint2(bf2_pack(v0.x, v0.y), bf2_pack(v0.z, v0.w));
        ((uint2*)g_Ah)[base + 1024] = make_uint2(bf2_pack(v1.x, v1.y), bf2_pack(v1.z, v1.w));
    }
}

// ---------------------------------------------------------------------------
// mma.sync bf16 GEMM: logits[M,N] = A @ W + bias, fp16 store.
// CTA 128x128, 8 warps (64x32 each), BK=64, 3-stage cp.async ring.
// ---------------------------------------------------------------------------
#define BM 128
#define BN 128
#define BKC 64
#define AROWB 144                     // 64 bf16 + pad
#define BROWB 272                     // 128 bf16 + pad
#define NCHUNK 8
#define STAGES 3
#define AB_OFF (BM * AROWB)           // 18432
#define STAGE_BYTES (AB_OFF + BKC * BROWB)   // 35840
#define GEMM_SMEM (STAGES * STAGE_BYTES)     // 107520

__global__ void __launch_bounds__(256, 2) mma_gemm_kernel(const float* __restrict__ bias) {
    extern __shared__ char smem[];
    uint32_t sbase = smem_u32(smem);

    int tid = threadIdx.x;
    int lane = tid & 31;
    int wid = tid >> 5;
    int wr = wid >> 2;
    int wc = wid & 3;
    int m0 = blockIdx.y * BM;
    int n0 = blockIdx.x * BN;

    float acc[4][4][4];
#pragma unroll
    for (int i = 0; i < 4; i++)
#pragma unroll
        for (int j = 0; j < 4; j++)
#pragma unroll
            for (int r = 0; r < 4; r++) acc[i][j][r] = 0.f;

    int rowA = tid >> 3, segA = tid & 7;
    int rowB = tid >> 4, segB = tid & 15;

#define LOAD_CHUNK(kc, st) do {                                               \
        int koff = (kc) * BKC;                                                \
        uint32_t sb = sbase + (st) * STAGE_BYTES;                             \
        _Pragma("unroll")                                                     \
        for (int p = 0; p < 4; p++) {                                         \
            int r = rowA + 32 * p;                                            \
            cp_async16(sb + r * AROWB + segA * 16,                            \
                       g_Ah + (size_t)(m0 + r) * KK + koff + segA * 8);       \
        }                                                                     \
        _Pragma("unroll")                                                     \
        for (int p = 0; p < 4; p++) {                                         \
            int r = rowB + 16 * p;                                            \
            cp_async16(sb + AB_OFF + r * BROWB + segB * 16,                   \
                       g_Wb + (size_t)(koff + r) * NN + n0 + segB * 8);       \
        }                                                                     \
    } while (0)

    LOAD_CHUNK(0, 0); asm volatile("cp.async.commit_group;");
    LOAD_CHUNK(1, 1); asm volatile("cp.async.commit_group;");

    uint32_t aoff = (uint32_t)((wr * 64 + (lane & 15)) * AROWB + (lane >> 4) * 16);
    uint32_t boff = (uint32_t)(AB_OFF + ((lane & 7) + ((lane >> 3) & 1) * 8) * BROWB
                               + (wc * 32 + (lane >> 4) * 8) * 2);

    for (int kc = 0; kc < NCHUNK; kc++) {
        asm volatile("cp.async.wait_group 1;");
        __syncthreads();

        if (kc + 2 < NCHUNK) LOAD_CHUNK(kc + 2, (kc + 2) % 3);
        asm volatile("cp.async.commit_group;");

        uint32_t stb = sbase + (kc % 3) * STAGE_BYTES;
        uint32_t aBase = stb + aoff;
        uint32_t bBase = stb + boff;
#pragma unroll
        for (int kk = 0; kk < 4; kk++) {
            uint32_t afr[4][4], bfr[2][4];
#pragma unroll
            for (int mi = 0; mi < 4; mi++)
                ldmatrix_x4(afr[mi], aBase + mi * 16 * AROWB + kk * 32);
#pragma unroll
            for (int nj = 0; nj < 2; nj++)
                ldmatrix_x4_trans(bfr[nj], bBase + kk * 16 * BROWB + nj * 32);
#pragma unroll
            for (int mi = 0; mi < 4; mi++)
#pragma unroll
                for (int ni = 0; ni < 4; ni++) {
                    uint32_t b0 = bfr[ni >> 1][(ni & 1) * 2];
                    uint32_t b1 = bfr[ni >> 1][(ni & 1) * 2 + 1];
                    mma16816(acc[mi][ni], afr[mi], b0, b1);
                }
        }
    }

    // Epilogue: bias add + fp16 store
    int l4 = lane >> 2, l2 = (lane & 3) * 2;
    float2 bb[4];
#pragma unroll
    for (int ni = 0; ni < 4; ni++) {
        int col = n0 + wc * 32 + ni * 8 + l2;
        bb[ni].x = __ldg(&bias[col]);
        bb[ni].y = __ldg(&bias[col + 1]);
    }
#pragma unroll
    for (int mi = 0; mi < 4; mi++) {
        int row = m0 + wr * 64 + mi * 16 + l4;
#pragma unroll
        for (int ni = 0; ni < 4; ni++) {
            int col = n0 + wc * 32 + ni * 8 + l2;
            __half2 h0 = __floats2half2_rn(acc[mi][ni][0] + bb[ni].x, acc[mi][ni][1] + bb[ni].y);
            __half2 h1 = __floats2half2_rn(acc[mi][ni][2] + bb[ni].x, acc[mi][ni][3] + bb[ni].y);
            *(__half2*)&g_logh[(size_t)row * NN + col] = h0;
            *(__half2*)&g_logh[(size_t)(row + 8) * NN + col] = h1;
        }
    }
}

// ---------------------------------------------------------------------------
// Exact fp32 rescore of one candidate column (warp-cooperative)
// ---------------------------------------------------------------------------
__device__ __forceinline__ float exact_score(const float* __restrict__ hidden,
                                             const float* __restrict__ W,
                                             const float* __restrict__ bias,
                                             const float* __restrict__ grow,
                                             int n, int col, int v, int lane) {
    const float* hrow = hidden + (size_t)n * KK;
    float s = 0.f;
#pragma unroll 4
    for (int j = lane; j < KK; j += 32)
        s = fmaf(hrow[j], W[(size_t)j * NN + col], s);
    for (int o = 16; o; o >>= 1) s += __shfl_xor_sync(0xffffffffu, s, o);
    return s + bias[col] + grow[v];
}

// ---------------------------------------------------------------------------
// Row kernel: warp handles 4 rows of one group with SOFTWARE PREFETCH —
// row q+1's raw logits/gumbels load during row q's compute. Marginal folded
// in registers, 10 smem atomics per warp. Last block computes perplexity.
// v-mapping: i -> v = 2*(lane + 32*(i/2)) + (i&1).
// ---------------------------------------------------------------------------
#define RESCORE_GAP  3.0e-2f
#define RESCORE_WIN  3.4e-2f
#define ROW_GRID 1024
#define ROW_THREADS 256

__global__ void __launch_bounds__(ROW_THREADS) row_kernel(const float* __restrict__ gumbels,
                                                          const float* __restrict__ cb,
                                                          float* __restrict__ out,
                                                          const float* __restrict__ hidden,
                                                          const float* __restrict__ W,
                                                          const float* __restrict__ bias,
                                                          int out_size) {
    __shared__ float smarg[NN];
    int tid = threadIdx.x;
    for (int i = tid; i < NN; i += ROW_THREADS) smarg[i] = 0.f;
    __syncthreads();

    int warpid = tid >> 5;              // 0..7
    int lane = tid & 31;
    int g = warpid & 1;
    int nbase = (blockIdx.x * 4 + (warpid >> 1)) * 4;   // 1024*4*4 = 16384 rows

#define VMAP(i) (2 * (lane + 32 * ((i) >> 1)) + ((i) & 1))

    float mreg[10];
#pragma unroll
    for (int i = 0; i < 10; i++) mreg[i] = 0.f;

    // raw prefetch buffers for one row
    uint32_t plh[5];
    float2 pg[5];

#define LOAD_RAW(nrow) do {                                                   \
        const uint32_t* lr = (const uint32_t*)(g_logh + (size_t)(nrow) * NN + g * VV); \
        const float2* gr = (const float2*)(gumbels + ((size_t)(nrow) * 2 + g) * VV);   \
        _Pragma("unroll")                                                     \
        for (int j = 0; j < 5; j++) {                                         \
            plh[j] = lr[lane + 32 * j];                                       \
            pg[j]  = gr[lane + 32 * j];                                       \
        }                                                                     \
    } while (0)

    LOAD_RAW(nbase);

    for (int q = 0; q < 4; q++) {
        int n = nbase + q;

        // unpack current row, then immediately issue next row's loads
        float l[10], sc[10];
#pragma unroll
        for (int j = 0; j < 5; j++) {
            float2 lf = __half22float2(*(const __half2*)&plh[j]);
            l[2 * j] = lf.x;     l[2 * j + 1] = lf.y;
            sc[2 * j] = lf.x + pg[j].x;
            sc[2 * j + 1] = lf.y + pg[j].y;
        }
        if (q < 3) LOAD_RAW(n + 1);

        // argmax of logits + gumbels
        float best = -3.4e38f;
        int bidx = 0;
#pragma unroll
        for (int i = 0; i < 10; i++) {
            int v = VMAP(i);
            if (sc[i] > best || (sc[i] == best && v < bidx)) { best = sc[i]; bidx = v; }
        }
        for (int o = 16; o; o >>= 1) {
            float ob = __shfl_down_sync(0xffffffffu, best, o);
            int oi   = __shfl_down_sync(0xffffffffu, bidx, o);
            if (ob > best || (ob == best && oi < bidx)) { best = ob; bidx = oi; }
        }
        best = __shfl_sync(0xffffffffu, best, 0);
        bidx = __shfl_sync(0xffffffffu, bidx, 0);

        // second best (excluding bidx)
        float sec = -3.4e38f;
#pragma unroll
        for (int i = 0; i < 10; i++) {
            int v = VMAP(i);
            if (v != bidx && sc[i] > sec) sec = sc[i];
        }
        for (int o = 16; o; o >>= 1) sec = fmaxf(sec, __shfl_xor_sync(0xffffffffu, sec, o));

        // near-tie: exact fp32 rescore of candidates within the window
        if (best - sec < RESCORE_GAP) {
            const float* grow = gumbels + ((size_t)n * 2 + g) * VV;
            float thr = best - RESCORE_WIN;
            float exbest = -3.4e38f;
            int exidx = VV;
            int col0 = g * VV;
#pragma unroll
            for (int i = 0; i < 10; i++) {
                unsigned mset = __ballot_sync(0xffffffffu, sc[i] >= thr);
                while (mset) {
                    int src = __ffs(mset) - 1;
                    mset &= mset - 1;
                    int v = 2 * (src + 32 * (i >> 1)) + (i & 1);
                    float ex = exact_score(hidden, W, bias, grow, n, col0 + v, v, lane);
                    if (ex > exbest || (ex == exbest && v < exidx)) { exbest = ex; exidx = v; }
                }
            }
            bidx = exidx;
        }

        // softmax(logits) for marginal
        float mx = l[0];
#pragma unroll
        for (int i = 1; i < 10; i++) mx = fmaxf(mx, l[i]);
        for (int o = 16; o; o >>= 1) mx = fmaxf(mx, __shfl_xor_sync(0xffffffffu, mx, o));
        float e[10];
        float sum = 0.f;
#pragma unroll
        for (int i = 0; i < 10; i++) { e[i] = __expf(l[i] - mx); sum += e[i]; }
        for (int o = 16; o; o >>= 1) sum += __shfl_xor_sync(0xffffffffu, sum, o);

        if (g_maskf[n] != 0.f) {
            float inv = 1.f / sum;
#pragma unroll
            for (int i = 0; i < 10; i++) mreg[i] = fmaf(e[i], inv, mreg[i]);
        }

        // codevector gather
        const float4* c4 = (const float4*)(cb + (size_t)(g * VV + bidx) * DG);
        float4* o4 = (float4*)(out + (size_t)n * 256 + g * DG);
        o4[lane] = c4[lane];
    }

    // one batch of smem atomics per warp (4 rows folded in registers)
#pragma unroll
    for (int i = 0; i < 10; i++)
        atomicAdd(&smarg[g * VV + VMAP(i)], mreg[i]);

    __syncthreads();
    for (int i = tid; i < NN; i += ROW_THREADS) atomicAdd(&g_marginal[i], smarg[i]);

    // ---- merged finalization: last block computes perplexity ----
    __shared__ int amLast;
    __threadfence();
    __syncthreads();
    if (tid == 0) amLast = (atomicAdd(&g_done, 1) == ROW_GRID - 1);
    __syncthreads();
    if (amLast) {
        __threadfence();   // acquire marginal written by all blocks
        __shared__ float s2[2];
        if (tid < 2) s2[tid] = 0.f;
        __syncthreads();
        float t0 = 0.f, t1 = 0.f;
        for (int i = tid; i < NN; i += ROW_THREADS) {
            float val = g_marginal[i] / g_msum;
            float t = val * logf(val + 1e-7f);
            if (i < VV) t0 += t; else t1 += t;
        }
        for (int o = 16; o; o >>= 1) {
            t0 += __shfl_xor_sync(0xffffffffu, t0, o);
            t1 += __shfl_xor_sync(0xffffffffu, t1, o);
        }
        if (lane == 0) { atomicAdd(&s2[0], t0); atomicAdd(&s2[1], t1); }
        __syncthreads();
        if (tid == 0) {
            out[out_size - 1] = expf(-s2[0]) + expf(-s2[1]);
            g_done = 0;   // reset for next graph replay
        }
    }
}

// ---------------------------------------------------------------------------
extern "C" void kernel_launch(void* const* d_in, const int* in_sizes, int n_in,
                              void* d_out, int out_size) {
    const float* hidden = (const float*)d_in[0];   // [8,2048,512]
    const void*  mask   = d_in[1];                 // [8,2048]
    const float* W      = (const float*)d_in[2];   // [512,640]
    const float* b      = (const float*)d_in[3];   // [640]
    const float* cb     = (const float*)d_in[4];   // [1,640,128]
    const float* gum    = (const float*)d_in[5];   // [32768,320]
    float* out = (float*)d_out;

    cudaFuncSetAttribute(mma_gemm_kernel,
                         cudaFuncAttributeMaxDynamicSharedMemorySize, GEMM_SMEM);

    pre_kernel<<<PRE_GRID, 1024>>>(hidden, W, mask);

    dim3 ggrid(NN / BN, MM / BM);   // (5, 128)
    mma_gemm_kernel<<<ggrid, 256, GEMM_SMEM>>>(b);

    row_kernel<<<ROW_GRID, ROW_THREADS>>>(gum, cb, out, hidden, W, b, out_size);
}

// round 16
// speedup vs baseline: 1.2648x; 1.0211x over previous
#include <cuda_runtime.h>
#include <cuda_bf16.h>
#include <cuda_fp16.h>
#include <cstdint>

// Problem constants: B=8, S=2048, H=512, G=2, V=320, D=256
#define MM 16384      // B*S
#define KK 512        // H
#define NN 640        // G*V
#define VV 320
#define DG 128        // D/G

// ---------------------------------------------------------------------------
// Scratch (static device globals: allocation-free)
// ---------------------------------------------------------------------------
__device__ __half g_logh[(size_t)MM * NN];                  // 20 MB fp16 logits
__device__ __half g_Ah[(size_t)MM * KK];                    // hidden fp16 [M,K]
__device__ __half g_Wb[(size_t)KK * NN];                    // W fp16 [K,N]
__device__ float g_marginal[NN];
__device__ float g_maskf[MM];
__device__ float g_msum;
__device__ int g_done;                                       // zero-init; reset by last block

__device__ __forceinline__ uint32_t smem_u32(const void* p) {
    uint32_t a;
    asm("{ .reg .u64 t; cvta.to.shared.u64 t, %1; cvt.u32.u64 %0, t; }" : "=r"(a) : "l"(p));
    return a;
}
__device__ __forceinline__ void cp_async16(uint32_t saddr, const void* gaddr) {
    asm volatile("cp.async.cg.shared.global [%0], [%1], 16;" :: "r"(saddr), "l"(gaddr));
}
__device__ __forceinline__ void ldmatrix_x4(uint32_t* r, uint32_t addr) {
    asm volatile("ldmatrix.sync.aligned.m8n8.x4.shared.b16 {%0,%1,%2,%3}, [%4];"
                 : "=r"(r[0]), "=r"(r[1]), "=r"(r[2]), "=r"(r[3]) : "r"(addr));
}
__device__ __forceinline__ void ldmatrix_x4_trans(uint32_t* r, uint32_t addr) {
    asm volatile("ldmatrix.sync.aligned.m8n8.x4.trans.shared.b16 {%0,%1,%2,%3}, [%4];"
                 : "=r"(r[0]), "=r"(r[1]), "=r"(r[2]), "=r"(r[3]) : "r"(addr));
}
// fp16 in, fp16 accumulate
__device__ __forceinline__ void mma16816_f16(uint32_t* c, const uint32_t* a,
                                             uint32_t b0, uint32_t b1) {
    asm volatile("mma.sync.aligned.m16n8k16.row.col.f16.f16.f16.f16 "
                 "{%0,%1}, {%2,%3,%4,%5}, {%6,%7}, {%0,%1};"
                 : "+r"(c[0]), "+r"(c[1])
                 : "r"(a[0]), "r"(a[1]), "r"(a[2]), "r"(a[3]), "r"(b0), "r"(b1));
}
__device__ __forceinline__ uint32_t h2_pack(float x, float y) {
    __half2 h = __floats2half2_rn(x, y);
    return *(uint32_t*)&h;
}

// ---------------------------------------------------------------------------
// Fused pre-pass:
//   block 0         : init (zero marginal, VECTORIZED mask detect/expand/sum)
//   blocks 1..80    : convert W fp32 [K,N] -> fp16 [K,N] (float4, coalesced)
//   blocks 81..592  : convert hidden fp32 -> fp16 (4 float4 per thread, ILP 4)
// ---------------------------------------------------------------------------
#define W4_BLOCKS 80                  // NN*KK/4 / 1024
#define A4_BLOCKS 512                 // MM*KK/4 / 4096
#define PRE_GRID (1 + W4_BLOCKS + A4_BLOCKS)

__global__ void __launch_bounds__(1024) pre_kernel(const float* __restrict__ A,
                                                   const float* __restrict__ W,
                                                   const void* __restrict__ maskraw) {
    int bx = blockIdx.x;
    int tid = threadIdx.x;

    if (bx == 0) {
        if (tid < NN) g_marginal[tid] = 0.f;

        __shared__ int isU8;
        if (tid == 0) isU8 = 0;
        __syncthreads();

        // Detection: one uint4 per thread covers bytes 16*tid..16*tid+15.
        const uint4* m16 = (const uint4*)maskraw;
        uint4 d = m16[tid];
        if (((d.x | d.y | d.z | d.w) & 0xFFFFFF00u) != 0u) isU8 = 1;
        __syncthreads();

        float local = 0.f;
        if (isU8) {
            unsigned wv[4] = {d.x, d.y, d.z, d.w};
            float4 st[4];
#pragma unroll
            for (int wd = 0; wd < 4; wd++) {
                float* f = (float*)&st[wd];
#pragma unroll
                for (int byt = 0; byt < 4; byt++) {
                    float v = ((wv[wd] >> (8 * byt)) & 0xFFu) ? 1.f : 0.f;
                    f[byt] = v;
                    local += v;
                }
            }
#pragma unroll
            for (int wd = 0; wd < 4; wd++)
                *(float4*)&g_maskf[tid * 16 + wd * 4] = st[wd];
        } else {
            const uint4* mi4 = (const uint4*)maskraw;
#pragma unroll
            for (int it = 0; it < 4; it++) {
                uint4 wv = mi4[tid + it * 1024];
                int base = 4 * (tid + it * 1024);
                float4 st;
                st.x = wv.x ? 1.f : 0.f;
                st.y = wv.y ? 1.f : 0.f;
                st.z = wv.z ? 1.f : 0.f;
                st.w = wv.w ? 1.f : 0.f;
                local += st.x + st.y + st.z + st.w;
                *(float4*)&g_maskf[base] = st;
            }
        }

        __shared__ float red[32];
        for (int o = 16; o; o >>= 1) local += __shfl_xor_sync(0xffffffffu, local, o);
        if ((tid & 31) == 0) red[tid >> 5] = local;
        __syncthreads();
        if (tid < 32) {
            float s = red[tid];
            for (int o = 16; o; o >>= 1) s += __shfl_xor_sync(0xffffffffu, s, o);
            if (tid == 0) g_msum = s;
        }
        return;
    }

    if (bx <= W4_BLOCKS) {
        size_t i4 = (size_t)(bx - 1) * 1024 + tid;             // over NN*KK/4
        float4 v = ((const float4*)W)[i4];
        ((uint2*)g_Wb)[i4] = make_uint2(h2_pack(v.x, v.y), h2_pack(v.z, v.w));
    } else {
        size_t base = (size_t)(bx - 1 - W4_BLOCKS) * 4096 + tid; // over MM*KK/4
#pragma unroll
        for (int u = 0; u < 4; u++) {
            size_t i4 = base + u * 1024;
            float4 v = ((const float4*)A)[i4];
            ((uint2*)g_Ah)[i4] = make_uint2(h2_pack(v.x, v.y), h2_pack(v.z, v.w));
        }
    }
}

// ---------------------------------------------------------------------------
// mma.sync fp16 GEMM (fp16 accumulate): logits[M,N] = A @ W + bias.
// CTA 128x128, 8 warps (64x32 each), BK=64, 3-stage cp.async ring.
// A: m-major smem (pitch 144B), non-trans ldsm. B: k-major smem (pitch 272B),
// trans ldsm from the [K,N] fp16 copy of W. Epilogue: __hadd2 bias, store fp16.
// ---------------------------------------------------------------------------
#define BM 128
#define BN 128
#define BKC 64
#define AROWB 144                     // 64 fp16 + pad
#define BROWB 272                     // 128 fp16 + pad
#define NCHUNK 8
#define STAGES 3
#define AB_OFF (BM * AROWB)           // 18432
#define STAGE_BYTES (AB_OFF + BKC * BROWB)   // 35840
#define GEMM_SMEM (STAGES * STAGE_BYTES)     // 107520

__global__ void __launch_bounds__(256, 2) mma_gemm_kernel(const float* __restrict__ bias) {
    extern __shared__ char smem[];
    uint32_t sbase = smem_u32(smem);

    int tid = threadIdx.x;
    int lane = tid & 31;
    int wid = tid >> 5;
    int wr = wid >> 2;
    int wc = wid & 3;
    int m0 = blockIdx.y * BM;
    int n0 = blockIdx.x * BN;

    uint32_t acc2[4][4][2];           // fp16x2 accumulators (4 halves per mma)
#pragma unroll
    for (int i = 0; i < 4; i++)
#pragma unroll
        for (int j = 0; j < 4; j++) { acc2[i][j][0] = 0u; acc2[i][j][1] = 0u; }

    int rowA = tid >> 3, segA = tid & 7;
    int rowB = tid >> 4, segB = tid & 15;

#define LOAD_CHUNK(kc, st) do {                                               \
        int koff = (kc) * BKC;                                                \
        uint32_t sb = sbase + (st) * STAGE_BYTES;                             \
        _Pragma("unroll")                                                     \
        for (int p = 0; p < 4; p++) {                                         \
            int r = rowA + 32 * p;                                            \
            cp_async16(sb + r * AROWB + segA * 16,                            \
                       g_Ah + (size_t)(m0 + r) * KK + koff + segA * 8);       \
        }                                                                     \
        _Pragma("unroll")                                                     \
        for (int p = 0; p < 4; p++) {                                         \
            int r = rowB + 16 * p;                                            \
            cp_async16(sb + AB_OFF + r * BROWB + segB * 16,                   \
                       g_Wb + (size_t)(koff + r) * NN + n0 + segB * 8);       \
        }                                                                     \
    } while (0)

    LOAD_CHUNK(0, 0); asm volatile("cp.async.commit_group;");
    LOAD_CHUNK(1, 1); asm volatile("cp.async.commit_group;");

    uint32_t aoff = (uint32_t)((wr * 64 + (lane & 15)) * AROWB + (lane >> 4) * 16);
    uint32_t boff = (uint32_t)(AB_OFF + ((lane & 7) + ((lane >> 3) & 1) * 8) * BROWB
                               + (wc * 32 + (lane >> 4) * 8) * 2);

    for (int kc = 0; kc < NCHUNK; kc++) {
        asm volatile("cp.async.wait_group 1;");
        __syncthreads();

        if (kc + 2 < NCHUNK) LOAD_CHUNK(kc + 2, (kc + 2) % 3);
        asm volatile("cp.async.commit_group;");

        uint32_t stb = sbase + (kc % 3) * STAGE_BYTES;
        uint32_t aBase = stb + aoff;
        uint32_t bBase = stb + boff;
#pragma unroll
        for (int kk = 0; kk < 4; kk++) {
            uint32_t afr[4][4], bfr[2][4];
#pragma unroll
            for (int mi = 0; mi < 4; mi++)
                ldmatrix_x4(afr[mi], aBase + mi * 16 * AROWB + kk * 32);
#pragma unroll
            for (int nj = 0; nj < 2; nj++)
                ldmatrix_x4_trans(bfr[nj], bBase + kk * 16 * BROWB + nj * 32);
#pragma unroll
            for (int mi = 0; mi < 4; mi++)
#pragma unroll
                for (int ni = 0; ni < 4; ni++) {
                    uint32_t b0 = bfr[ni >> 1][(ni & 1) * 2];
                    uint32_t b1 = bfr[ni >> 1][(ni & 1) * 2 + 1];
                    mma16816_f16(acc2[mi][ni], afr[mi], b0, b1);
                }
        }
    }

    // Epilogue: fp16 bias add + store (acc already fp16)
    int l4 = lane >> 2, l2 = (lane & 3) * 2;
    __half2 bb2[4];
#pragma unroll
    for (int ni = 0; ni < 4; ni++) {
        int col = n0 + wc * 32 + ni * 8 + l2;
        bb2[ni] = __floats2half2_rn(__ldg(&bias[col]), __ldg(&bias[col + 1]));
    }
#pragma unroll
    for (int mi = 0; mi < 4; mi++) {
        int row = m0 + wr * 64 + mi * 16 + l4;
#pragma unroll
        for (int ni = 0; ni < 4; ni++) {
            int col = n0 + wc * 32 + ni * 8 + l2;
            __half2 h0 = __hadd2(*(__half2*)&acc2[mi][ni][0], bb2[ni]);
            __half2 h1 = __hadd2(*(__half2*)&acc2[mi][ni][1], bb2[ni]);
            *(__half2*)&g_logh[(size_t)row * NN + col] = h0;
            *(__half2*)&g_logh[(size_t)(row + 8) * NN + col] = h1;
        }
    }
}

// ---------------------------------------------------------------------------
// Exact fp32 rescore of one candidate column (warp-cooperative)
// ---------------------------------------------------------------------------
__device__ __forceinline__ float exact_score(const float* __restrict__ hidden,
                                             const float* __restrict__ W,
                                             const float* __restrict__ bias,
                                             const float* __restrict__ grow,
                                             int n, int col, int v, int lane) {
    const float* hrow = hidden + (size_t)n * KK;
    float s = 0.f;
#pragma unroll 4
    for (int j = lane; j < KK; j += 32)
        s = fmaf(hrow[j], W[(size_t)j * NN + col], s);
    for (int o = 16; o; o >>= 1) s += __shfl_xor_sync(0xffffffffu, s, o);
    return s + bias[col] + grow[v];
}

// ---------------------------------------------------------------------------
// Row kernel: warp handles 4 rows with prefetch; fused top-2 butterfly
// reduction; softmax without max-subtraction (logits are O(1)); exp skipped
// for unmasked rows. Marginal folded in registers; last block finalizes.
// v-mapping: i -> v = 2*(lane + 32*(i/2)) + (i&1).
// ---------------------------------------------------------------------------
#define RESCORE_GAP  3.0e-2f
#define RESCORE_WIN  3.4e-2f
#define ROW_GRID 1024
#define ROW_THREADS 256

__global__ void __launch_bounds__(ROW_THREADS) row_kernel(const float* __restrict__ gumbels,
                                                          const float* __restrict__ cb,
                                                          float* __restrict__ out,
                                                          const float* __restrict__ hidden,
                                                          const float* __restrict__ W,
                                                          const float* __restrict__ bias,
                                                          int out_size) {
    __shared__ float smarg[NN];
    int tid = threadIdx.x;
    for (int i = tid; i < NN; i += ROW_THREADS) smarg[i] = 0.f;
    __syncthreads();

    int warpid = tid >> 5;              // 0..7
    int lane = tid & 31;
    int g = warpid & 1;
    int nbase = (blockIdx.x * 4 + (warpid >> 1)) * 4;   // 1024*4*4 = 16384 rows

#define VMAP(i) (2 * (lane + 32 * ((i) >> 1)) + ((i) & 1))

    float mreg[10];
#pragma unroll
    for (int i = 0; i < 10; i++) mreg[i] = 0.f;

    // raw prefetch buffers for one row
    uint32_t plh[5];
    float2 pg[5];

#define LOAD_RAW(nrow) do {                                                   \
        const uint32_t* lr = (const uint32_t*)(g_logh + (size_t)(nrow) * NN + g * VV); \
        const float2* gr = (const float2*)(gumbels + ((size_t)(nrow) * 2 + g) * VV);   \
        _Pragma("unroll")                                                     \
        for (int j = 0; j < 5; j++) {                                         \
            plh[j] = lr[lane + 32 * j];                                       \
            pg[j]  = gr[lane + 32 * j];                                       \
        }                                                                     \
    } while (0)

    LOAD_RAW(nbase);

    for (int q = 0; q < 4; q++) {
        int n = nbase + q;

        float l[10], sc[10];
#pragma unroll
        for (int j = 0; j < 5; j++) {
            float2 lf = __half22float2(*(const __half2*)&plh[j]);
            l[2 * j] = lf.x;     l[2 * j + 1] = lf.y;
            sc[2 * j] = lf.x + pg[j].x;
            sc[2 * j + 1] = lf.y + pg[j].y;
        }
        if (q < 3) LOAD_RAW(n + 1);

        // fused top-2 scan (per-lane)
        float b = -3.4e38f, s = -3.4e38f;
        int bi = 0;
#pragma unroll
        for (int i = 0; i < 10; i++) {
            int v = VMAP(i);
            if (sc[i] > b || (sc[i] == b && v < bi)) { s = fmaxf(s, b); b = sc[i]; bi = v; }
            else s = fmaxf(s, sc[i]);
        }
        // butterfly top-2 merge: all lanes converge to (best, bestidx, sec)
        for (int o = 16; o; o >>= 1) {
            float b2 = __shfl_xor_sync(0xffffffffu, b, o);
            int bi2   = __shfl_xor_sync(0xffffffffu, bi, o);
            float s2 = __shfl_xor_sync(0xffffffffu, s, o);
            if (b2 > b || (b2 == b && bi2 < bi)) {
                s = fmaxf(fmaxf(s, s2), b);
                b = b2; bi = bi2;
            } else {
                s = fmaxf(fmaxf(s, s2), b2);
            }
        }
        int bidx = bi;

        // near-tie: exact fp32 rescore of candidates within the window
        if (b - s < RESCORE_GAP) {
            const float* grow = gumbels + ((size_t)n * 2 + g) * VV;
            float thr = b - RESCORE_WIN;
            float exbest = -3.4e38f;
            int exidx = VV;
            int col0 = g * VV;
#pragma unroll
            for (int i = 0; i < 10; i++) {
                unsigned mset = __ballot_sync(0xffffffffu, sc[i] >= thr);
                while (mset) {
                    int src = __ffs(mset) - 1;
                    mset &= mset - 1;
                    int v = 2 * (src + 32 * (i >> 1)) + (i & 1);
                    float ex = exact_score(hidden, W, bias, grow, n, col0 + v, v, lane);
                    if (ex > exbest || (ex == exbest && v < exidx)) { exbest = ex; exidx = v; }
                }
            }
            bidx = exidx;
        }

        // masked softmax (no max-subtraction; logits are O(1))
        if (g_maskf[n] != 0.f) {
            float e[10];
            float sum = 0.f;
#pragma unroll
            for (int i = 0; i < 10; i++) { e[i] = __expf(l[i]); sum += e[i]; }
            for (int o = 16; o; o >>= 1) sum += __shfl_xor_sync(0xffffffffu, sum, o);
            float inv = 1.f / sum;
#pragma unroll
            for (int i = 0; i < 10; i++) mreg[i] = fmaf(e[i], inv, mreg[i]);
        }

        // codevector gather
        const float4* c4 = (const float4*)(cb + (size_t)(g * VV + bidx) * DG);
        float4* o4 = (float4*)(out + (size_t)n * 256 + g * DG);
        o4[lane] = c4[lane];
    }

    // one batch of smem atomics per warp (4 rows folded in registers)
#pragma unroll
    for (int i = 0; i < 10; i++)
        atomicAdd(&smarg[g * VV + VMAP(i)], mreg[i]);

    __syncthreads();
    for (int i = tid; i < NN; i += ROW_THREADS) atomicAdd(&g_marginal[i], smarg[i]);

    // ---- merged finalization: last block computes perplexity ----
    __shared__ int amLast;
    __threadfence();
    __syncthreads();
    if (tid == 0) amLast = (atomicAdd(&g_done, 1) == ROW_GRID - 1);
    __syncthreads();
    if (amLast) {
        __threadfence();   // acquire marginal written by all blocks
        __shared__ float s2[2];
        if (tid < 2) s2[tid] = 0.f;
        __syncthreads();
        float t0 = 0.f, t1 = 0.f;
        for (int i = tid; i < NN; i += ROW_THREADS) {
            float val = g_marginal[i] / g_msum;
            float t = val * logf(val + 1e-7f);
            if (i < VV) t0 += t; else t1 += t;
        }
        for (int o = 16; o; o >>= 1) {
            t0 += __shfl_xor_sync(0xffffffffu, t0, o);
            t1 += __shfl_xor_sync(0xffffffffu, t1, o);
        }
        if (lane == 0) { atomicAdd(&s2[0], t0); atomicAdd(&s2[1], t1); }
        __syncthreads();
        if (tid == 0) {
            out[out_size - 1] = expf(-s2[0]) + expf(-s2[1]);
            g_done = 0;   // reset for next graph replay
        }
    }
}

// ---------------------------------------------------------------------------
extern "C" void kernel_launch(void* const* d_in, const int* in_sizes, int n_in,
                              void* d_out, int out_size) {
    const float* hidden = (const float*)d_in[0];   // [8,2048,512]
    const void*  mask   = d_in[1];                 // [8,2048]
    const float* W      = (const float*)d_in[2];   // [512,640]
    const float* b      = (const float*)d_in[3];   // [640]
    const float* cb     = (const float*)d_in[4];   // [1,640,128]
    const float* gum    = (const float*)d_in[5];   // [32768,320]
    float* out = (float*)d_out;

    cudaFuncSetAttribute(mma_gemm_kernel,
                         cudaFuncAttributeMaxDynamicSharedMemorySize, GEMM_SMEM);

    pre_kernel<<<PRE_GRID, 1024>>>(hidden, W, mask);

    dim3 ggrid(NN / BN, MM / BM);   // (5, 128)
    mma_gemm_kernel<<<ggrid, 256, GEMM_SMEM>>>(b);

    row_kernel<<<ROW_GRID, ROW_THREADS>>>(gum, cb, out, hidden, W, b, out_size);
}

// round 17
// speedup vs baseline: 1.3310x; 1.0523x over previous
#include <cuda_runtime.h>
#include <cuda_bf16.h>
#include <cuda_fp16.h>
#include <cstdint>

// Problem constants: B=8, S=2048, H=512, G=2, V=320, D=256
#define MM 16384      // B*S
#define KK 512        // H
#define NN 640        // G*V
#define VV 320
#define DG 128        // D/G

// ---------------------------------------------------------------------------
// Scratch (static device globals: allocation-free)
// ---------------------------------------------------------------------------
__device__ __half g_logh[(size_t)MM * NN];                  // 20 MB fp16 logits
__device__ __half g_Ah[(size_t)MM * KK];                    // hidden fp16 [M,K]
__device__ __half g_Wb[(size_t)KK * NN];                    // W fp16 [K,N]
__device__ float g_marginal[NN];
__device__ float g_maskf[MM];
__device__ float g_msum;
__device__ int g_done;                                       // zero-init; reset by last block

__device__ __forceinline__ uint32_t smem_u32(const void* p) {
    uint32_t a;
    asm("{ .reg .u64 t; cvta.to.shared.u64 t, %1; cvt.u32.u64 %0, t; }" : "=r"(a) : "l"(p));
    return a;
}
__device__ __forceinline__ void cp_async16(uint32_t saddr, const void* gaddr) {
    asm volatile("cp.async.cg.shared.global [%0], [%1], 16;" :: "r"(saddr), "l"(gaddr));
}
__device__ __forceinline__ void ldmatrix_x4(uint32_t* r, uint32_t addr) {
    asm volatile("ldmatrix.sync.aligned.m8n8.x4.shared.b16 {%0,%1,%2,%3}, [%4];"
                 : "=r"(r[0]), "=r"(r[1]), "=r"(r[2]), "=r"(r[3]) : "r"(addr));
}
__device__ __forceinline__ void ldmatrix_x4_trans(uint32_t* r, uint32_t addr) {
    asm volatile("ldmatrix.sync.aligned.m8n8.x4.trans.shared.b16 {%0,%1,%2,%3}, [%4];"
                 : "=r"(r[0]), "=r"(r[1]), "=r"(r[2]), "=r"(r[3]) : "r"(addr));
}
// fp16 in, fp16 accumulate
__device__ __forceinline__ void mma16816_f16(uint32_t* c, const uint32_t* a,
                                             uint32_t b0, uint32_t b1) {
    asm volatile("mma.sync.aligned.m16n8k16.row.col.f16.f16.f16.f16 "
                 "{%0,%1}, {%2,%3,%4,%5}, {%6,%7}, {%0,%1};"
                 : "+r"(c[0]), "+r"(c[1])
                 : "r"(a[0]), "r"(a[1]), "r"(a[2]), "r"(a[3]), "r"(b0), "r"(b1));
}
__device__ __forceinline__ uint32_t h2_pack(float x, float y) {
    __half2 h = __floats2half2_rn(x, y);
    return *(uint32_t*)&h;
}

// ---------------------------------------------------------------------------
// Fused pre-pass:
//   block 0         : init (zero marginal, VECTORIZED mask detect/expand/sum)
//   blocks 1..80    : convert W fp32 [K,N] -> fp16 [K,N] (float4, coalesced)
//   blocks 81..592  : convert hidden fp32 -> fp16 (4 float4 per thread, ILP 4)
// ---------------------------------------------------------------------------
#define W4_BLOCKS 80                  // NN*KK/4 / 1024
#define A4_BLOCKS 512                 // MM*KK/4 / 4096
#define PRE_GRID (1 + W4_BLOCKS + A4_BLOCKS)

__global__ void __launch_bounds__(1024) pre_kernel(const float* __restrict__ A,
                                                   const float* __restrict__ W,
                                                   const void* __restrict__ maskraw) {
    int bx = blockIdx.x;
    int tid = threadIdx.x;

    if (bx == 0) {
        if (tid < NN) g_marginal[tid] = 0.f;

        __shared__ int isU8;
        if (tid == 0) isU8 = 0;
        __syncthreads();

        // Detection: one uint4 per thread covers bytes 16*tid..16*tid+15.
        const uint4* m16 = (const uint4*)maskraw;
        uint4 d = m16[tid];
        if (((d.x | d.y | d.z | d.w) & 0xFFFFFF00u) != 0u) isU8 = 1;
        __syncthreads();

        float local = 0.f;
        if (isU8) {
            unsigned wv[4] = {d.x, d.y, d.z, d.w};
            float4 st[4];
#pragma unroll
            for (int wd = 0; wd < 4; wd++) {
                float* f = (float*)&st[wd];
#pragma unroll
                for (int byt = 0; byt < 4; byt++) {
                    float v = ((wv[wd] >> (8 * byt)) & 0xFFu) ? 1.f : 0.f;
                    f[byt] = v;
                    local += v;
                }
            }
#pragma unroll
            for (int wd = 0; wd < 4; wd++)
                *(float4*)&g_maskf[tid * 16 + wd * 4] = st[wd];
        } else {
            const uint4* mi4 = (const uint4*)maskraw;
#pragma unroll
            for (int it = 0; it < 4; it++) {
                uint4 wv = mi4[tid + it * 1024];
                int base = 4 * (tid + it * 1024);
                float4 st;
                st.x = wv.x ? 1.f : 0.f;
                st.y = wv.y ? 1.f : 0.f;
                st.z = wv.z ? 1.f : 0.f;
                st.w = wv.w ? 1.f : 0.f;
                local += st.x + st.y + st.z + st.w;
                *(float4*)&g_maskf[base] = st;
            }
        }

        __shared__ float red[32];
        for (int o = 16; o; o >>= 1) local += __shfl_xor_sync(0xffffffffu, local, o);
        if ((tid & 31) == 0) red[tid >> 5] = local;
        __syncthreads();
        if (tid < 32) {
            float s = red[tid];
            for (int o = 16; o; o >>= 1) s += __shfl_xor_sync(0xffffffffu, s, o);
            if (tid == 0) g_msum = s;
        }
        return;
    }

    if (bx <= W4_BLOCKS) {
        size_t i4 = (size_t)(bx - 1) * 1024 + tid;             // over NN*KK/4
        float4 v = ((const float4*)W)[i4];
        ((uint2*)g_Wb)[i4] = make_uint2(h2_pack(v.x, v.y), h2_pack(v.z, v.w));
    } else {
        size_t base = (size_t)(bx - 1 - W4_BLOCKS) * 4096 + tid; // over MM*KK/4
#pragma unroll
        for (int u = 0; u < 4; u++) {
            size_t i4 = base + u * 1024;
            float4 v = ((const float4*)A)[i4];
            ((uint2*)g_Ah)[i4] = make_uint2(h2_pack(v.x, v.y), h2_pack(v.z, v.w));
        }
    }
}

// ---------------------------------------------------------------------------
// mma.sync fp16 GEMM (fp16 accumulate): logits[M,N] = A @ W + bias.
// CTA 128x128, 8 warps (64x32 each), BK=32, 3-stage cp.async ring,
// 3 CTAs/SM (56.8 KB smem, <=85 regs). 16 chunks, wait_group 1 pipeline.
// ---------------------------------------------------------------------------
#define BM 128
#define BN 128
#define BKC 32
#define AROWB 80                      // 32 fp16 + 16B pad
#define BROWB 272                     // 128 fp16 + pad
#define NCHUNK 16
#define STAGES 3
#define AB_OFF (BM * AROWB)           // 10240
#define STAGE_BYTES (AB_OFF + BKC * BROWB)   // 10240 + 8704 = 18944
#define GEMM_SMEM (STAGES * STAGE_BYTES)     // 56832

__global__ void __launch_bounds__(256, 3) mma_gemm_kernel(const float* __restrict__ bias) {
    extern __shared__ char smem[];
    uint32_t sbase = smem_u32(smem);

    int tid = threadIdx.x;
    int lane = tid & 31;
    int wid = tid >> 5;
    int wr = wid >> 2;
    int wc = wid & 3;
    int m0 = blockIdx.y * BM;
    int n0 = blockIdx.x * BN;

    uint32_t acc2[4][4][2];           // fp16x2 accumulators
#pragma unroll
    for (int i = 0; i < 4; i++)
#pragma unroll
        for (int j = 0; j < 4; j++) { acc2[i][j][0] = 0u; acc2[i][j][1] = 0u; }

    // A: 512 segs of 16B (128 rows x 4); B: 512 segs (32 rows x 16); 2 each
    int rA0 = tid >> 2, sA0 = tid & 3;
    int rB0 = tid >> 4, sB0 = tid & 15;

#define LOAD_CHUNK(kc, st) do {                                               \
        int koff = (kc) * BKC;                                                \
        uint32_t sb = sbase + (st) * STAGE_BYTES;                             \
        cp_async16(sb + rA0 * AROWB + sA0 * 16,                               \
                   g_Ah + (size_t)(m0 + rA0) * KK + koff + sA0 * 8);          \
        cp_async16(sb + (rA0 + 64) * AROWB + sA0 * 16,                        \
                   g_Ah + (size_t)(m0 + rA0 + 64) * KK + koff + sA0 * 8);     \
        cp_async16(sb + AB_OFF + rB0 * BROWB + sB0 * 16,                      \
                   g_Wb + (size_t)(koff + rB0) * NN + n0 + sB0 * 8);          \
        cp_async16(sb + AB_OFF + (rB0 + 16) * BROWB + sB0 * 16,               \
                   g_Wb + (size_t)(koff + rB0 + 16) * NN + n0 + sB0 * 8);     \
    } while (0)

    LOAD_CHUNK(0, 0); asm volatile("cp.async.commit_group;");
    LOAD_CHUNK(1, 1); asm volatile("cp.async.commit_group;");

    uint32_t aoff = (uint32_t)((wr * 64 + (lane & 15)) * AROWB + (lane >> 4) * 16);
    uint32_t boff = (uint32_t)(AB_OFF + ((lane & 7) + ((lane >> 3) & 1) * 8) * BROWB
                               + (wc * 32 + (lane >> 4) * 8) * 2);

    for (int kc = 0; kc < NCHUNK; kc++) {
        asm volatile("cp.async.wait_group 1;");   // chunk kc resident
        __syncthreads();

        if (kc + 2 < NCHUNK) LOAD_CHUNK(kc + 2, (kc + 2) % 3);
        asm volatile("cp.async.commit_group;");   // always commit

        uint32_t stb = sbase + (kc % 3) * STAGE_BYTES;
        uint32_t aBase = stb + aoff;
        uint32_t bBase = stb + boff;
#pragma unroll
        for (int kk = 0; kk < 2; kk++) {
            uint32_t afr[4][4], bfr[2][4];
#pragma unroll
            for (int mi = 0; mi < 4; mi++)
                ldmatrix_x4(afr[mi], aBase + mi * 16 * AROWB + kk * 32);
#pragma unroll
            for (int nj = 0; nj < 2; nj++)
                ldmatrix_x4_trans(bfr[nj], bBase + kk * 16 * BROWB + nj * 32);
#pragma unroll
            for (int mi = 0; mi < 4; mi++)
#pragma unroll
                for (int ni = 0; ni < 4; ni++) {
                    uint32_t b0 = bfr[ni >> 1][(ni & 1) * 2];
                    uint32_t b1 = bfr[ni >> 1][(ni & 1) * 2 + 1];
                    mma16816_f16(acc2[mi][ni], afr[mi], b0, b1);
                }
        }
    }

    // Epilogue: fp16 bias add + store (acc already fp16)
    int l4 = lane >> 2, l2 = (lane & 3) * 2;
    __half2 bb2[4];
#pragma unroll
    for (int ni = 0; ni < 4; ni++) {
        int col = n0 + wc * 32 + ni * 8 + l2;
        bb2[ni] = __floats2half2_rn(__ldg(&bias[col]), __ldg(&bias[col + 1]));
    }
#pragma unroll
    for (int mi = 0; mi < 4; mi++) {
        int row = m0 + wr * 64 + mi * 16 + l4;
#pragma unroll
        for (int ni = 0; ni < 4; ni++) {
            int col = n0 + wc * 32 + ni * 8 + l2;
            __half2 h0 = __hadd2(*(__half2*)&acc2[mi][ni][0], bb2[ni]);
            __half2 h1 = __hadd2(*(__half2*)&acc2[mi][ni][1], bb2[ni]);
            *(__half2*)&g_logh[(size_t)row * NN + col] = h0;
            *(__half2*)&g_logh[(size_t)(row + 8) * NN + col] = h1;
        }
    }
}

// ---------------------------------------------------------------------------
// Exact fp32 rescore of one candidate column (warp-cooperative)
// ---------------------------------------------------------------------------
__device__ __forceinline__ float exact_score(const float* __restrict__ hidden,
                                             const float* __restrict__ W,
                                             const float* __restrict__ bias,
                                             const float* __restrict__ grow,
                                             int n, int col, int v, int lane) {
    const float* hrow = hidden + (size_t)n * KK;
    float s = 0.f;
#pragma unroll 4
    for (int j = lane; j < KK; j += 32)
        s = fmaf(hrow[j], W[(size_t)j * NN + col], s);
    for (int o = 16; o; o >>= 1) s += __shfl_xor_sync(0xffffffffu, s, o);
    return s + bias[col] + grow[v];
}

// ---------------------------------------------------------------------------
// Row kernel: warp handles 4 rows with prefetch; fused top-2 butterfly
// reduction; softmax without max-subtraction; exp skipped for unmasked rows.
// Marginal folded in registers; last block finalizes perplexity.
// v-mapping: i -> v = 2*(lane + 32*(i/2)) + (i&1).
// ---------------------------------------------------------------------------
#define RESCORE_GAP  3.0e-2f
#define RESCORE_WIN  3.4e-2f
#define ROW_GRID 1024
#define ROW_THREADS 256

__global__ void __launch_bounds__(ROW_THREADS) row_kernel(const float* __restrict__ gumbels,
                                                          const float* __restrict__ cb,
                                                          float* __restrict__ out,
                                                          const float* __restrict__ hidden,
                                                          const float* __restrict__ W,
                                                          const float* __restrict__ bias,
                                                          int out_size) {
    __shared__ float smarg[NN];
    int tid = threadIdx.x;
    for (int i = tid; i < NN; i += ROW_THREADS) smarg[i] = 0.f;
    __syncthreads();

    int warpid = tid >> 5;              // 0..7
    int lane = tid & 31;
    int g = warpid & 1;
    int nbase = (blockIdx.x * 4 + (warpid >> 1)) * 4;   // 1024*4*4 = 16384 rows

#define VMAP(i) (2 * (lane + 32 * ((i) >> 1)) + ((i) & 1))

    float mreg[10];
#pragma unroll
    for (int i = 0; i < 10; i++) mreg[i] = 0.f;

    // raw prefetch buffers for one row
    uint32_t plh[5];
    float2 pg[5];

#define LOAD_RAW(nrow) do {                                                   \
        const uint32_t* lr = (const uint32_t*)(g_logh + (size_t)(nrow) * NN + g * VV); \
        const float2* gr = (const float2*)(gumbels + ((size_t)(nrow) * 2 + g) * VV);   \
        _Pragma("unroll")                                                     \
        for (int j = 0; j < 5; j++) {                                         \
            plh[j] = lr[lane + 32 * j];                                       \
            pg[j]  = gr[lane + 32 * j];                                       \
        }                                                                     \
    } while (0)

    LOAD_RAW(nbase);

    for (int q = 0; q < 4; q++) {
        int n = nbase + q;

        float l[10], sc[10];
#pragma unroll
        for (int j = 0; j < 5; j++) {
            float2 lf = __half22float2(*(const __half2*)&plh[j]);
            l[2 * j] = lf.x;     l[2 * j + 1] = lf.y;
            sc[2 * j] = lf.x + pg[j].x;
            sc[2 * j + 1] = lf.y + pg[j].y;
        }
        if (q < 3) LOAD_RAW(n + 1);

        // fused top-2 scan (per-lane)
        float b = -3.4e38f, s = -3.4e38f;
        int bi = 0;
#pragma unroll
        for (int i = 0; i < 10; i++) {
            int v = VMAP(i);
            if (sc[i] > b || (sc[i] == b && v < bi)) { s = fmaxf(s, b); b = sc[i]; bi = v; }
            else s = fmaxf(s, sc[i]);
        }
        // butterfly top-2 merge: all lanes converge to (best, bestidx, sec)
        for (int o = 16; o; o >>= 1) {
            float b2 = __shfl_xor_sync(0xffffffffu, b, o);
            int bi2   = __shfl_xor_sync(0xffffffffu, bi, o);
            float s2 = __shfl_xor_sync(0xffffffffu, s, o);
            if (b2 > b || (b2 == b && bi2 < bi)) {
                s = fmaxf(fmaxf(s, s2), b);
                b = b2; bi = bi2;
            } else {
                s = fmaxf(fmaxf(s, s2), b2);
            }
        }
        int bidx = bi;

        // near-tie: exact fp32 rescore of candidates within the window
        if (b - s < RESCORE_GAP) {
            const float* grow = gumbels + ((size_t)n * 2 + g) * VV;
            float thr = b - RESCORE_WIN;
            float exbest = -3.4e38f;
            int exidx = VV;
            int col0 = g * VV;
#pragma unroll
            for (int i = 0; i < 10; i++) {
                unsigned mset = __ballot_sync(0xffffffffu, sc[i] >= thr);
                while (mset) {
                    int src = __ffs(mset) - 1;
                    mset &= mset - 1;
                    int v = 2 * (src + 32 * (i >> 1)) + (i & 1);
                    float ex = exact_score(hidden, W, bias, grow, n, col0 + v, v, lane);
                    if (ex > exbest || (ex == exbest && v < exidx)) { exbest = ex; exidx = v; }
                }
            }
            bidx = exidx;
        }

        // masked softmax (no max-subtraction; logits are O(1))
        if (g_maskf[n] != 0.f) {
            float e[10];
            float sum = 0.f;
#pragma unroll
            for (int i = 0; i < 10; i++) { e[i] = __expf(l[i]); sum += e[i]; }
            for (int o = 16; o; o >>= 1) sum += __shfl_xor_sync(0xffffffffu, sum, o);
            float inv = 1.f / sum;
#pragma unroll
            for (int i = 0; i < 10; i++) mreg[i] = fmaf(e[i], inv, mreg[i]);
        }

        // codevector gather
        const float4* c4 = (const float4*)(cb + (size_t)(g * VV + bidx) * DG);
        float4* o4 = (float4*)(out + (size_t)n * 256 + g * DG);
        o4[lane] = c4[lane];
    }

    // one batch of smem atomics per warp (4 rows folded in registers)
#pragma unroll
    for (int i = 0; i < 10; i++)
        atomicAdd(&smarg[g * VV + VMAP(i)], mreg[i]);

    __syncthreads();
    for (int i = tid; i < NN; i += ROW_THREADS) atomicAdd(&g_marginal[i], smarg[i]);

    // ---- merged finalization: last block computes perplexity ----
    __shared__ int amLast;
    __threadfence();
    __syncthreads();
    if (tid == 0) amLast = (atomicAdd(&g_done, 1) == ROW_GRID - 1);
    __syncthreads();
    if (amLast) {
        __threadfence();   // acquire marginal written by all blocks
        __shared__ float s2[2];
        if (tid < 2) s2[tid] = 0.f;
        __syncthreads();
        float t0 = 0.f, t1 = 0.f;
        for (int i = tid; i < NN; i += ROW_THREADS) {
            float val = g_marginal[i] / g_msum;
            float t = val * logf(val + 1e-7f);
            if (i < VV) t0 += t; else t1 += t;
        }
        for (int o = 16; o; o >>= 1) {
            t0 += __shfl_xor_sync(0xffffffffu, t0, o);
            t1 += __shfl_xor_sync(0xffffffffu, t1, o);
        }
        if (lane == 0) { atomicAdd(&s2[0], t0); atomicAdd(&s2[1], t1); }
        __syncthreads();
        if (tid == 0) {
            out[out_size - 1] = expf(-s2[0]) + expf(-s2[1]);
            g_done = 0;   // reset for next graph replay
        }
    }
}

// ---------------------------------------------------------------------------
extern "C" void kernel_launch(void* const* d_in, const int* in_sizes, int n_in,
                              void* d_out, int out_size) {
    const float* hidden = (const float*)d_in[0];   // [8,2048,512]
    const void*  mask   = d_in[1];                 // [8,2048]
    const float* W      = (const float*)d_in[2];   // [512,640]
    const float* b      = (const float*)d_in[3];   // [640]
    const float* cb     = (const float*)d_in[4];   // [1,640,128]
    const float* gum    = (const float*)d_in[5];   // [32768,320]
    float* out = (float*)d_out;

    cudaFuncSetAttribute(mma_gemm_kernel,
                         cudaFuncAttributeMaxDynamicSharedMemorySize, GEMM_SMEM);

    pre_kernel<<<PRE_GRID, 1024>>>(hidden, W, mask);

    dim3 ggrid(NN / BN, MM / BM);   // (5, 128)
    mma_gemm_kernel<<<ggrid, 256, GEMM_SMEM>>>(b);

    row_kernel<<<ROW_GRID, ROW_THREADS>>>(gum, cb, out, hidden, W, b, out_size);
}